// round 14
// baseline (speedup 1.0000x reference)
#include <cuda_runtime.h>
#include <cuda.h>
#include <cuda_fp16.h>
#include <cuda_bf16.h>
#include <cstdint>
#include <math.h>

constexpr int BB = 2;
constexpr int CC = 512;
constexpr int NN = 4096;
constexpr int DD = 64;
constexpr int QK = 128;

// ---------------------------------------------------------------------------
// Scratch
// ---------------------------------------------------------------------------
__device__ __align__(1024) __half         g_qkh[(size_t)BB * NN * QK]; // fp16 q|k
__device__ __align__(1024) __nv_bfloat16  g_vb [(size_t)BB * CC * NN]; // bf16 v
__device__ __align__(1024) __half         g_xTh[(size_t)BB * NN * CC]; // fp16 xT
__device__ __align__(1024) __half         g_wrh[(size_t)CC * CC];      // fp16 Wv
__device__ __align__(1024) __half         g_wqkh[(size_t)QK * CC];     // fp16 Wq|Wk
__device__ __align__(1024) float          g_bqk[QK];
__device__ __align__(1024) __nv_bfloat16  g_eb [(size_t)BB * NN * NN]; // bf16 exp(s)
__device__ __align__(1024) float          g_rs [(size_t)BB * NN];      // fp32 row sums

// ---------------------------------------------------------------------------
// Helpers
// ---------------------------------------------------------------------------
__device__ __forceinline__ uint32_t smem_to_u32(const void* p) {
    uint32_t a;
    asm("{ .reg .u64 t; cvta.to.shared.u64 t, %1; cvt.u32.u64 %0, t; }"
        : "=r"(a) : "l"(p));
    return a;
}

#define MBARRIER_INIT(addr, cnt) \
    asm volatile("mbarrier.init.shared.b64 [%0], %1;" \
        :: "r"((uint32_t)(addr)), "r"((uint32_t)(cnt)) : "memory")
#define MBARRIER_EXPECT_TX(addr, bytes) \
    asm volatile("mbarrier.arrive.expect_tx.shared.b64 _, [%0], %1;" \
        :: "r"((uint32_t)(addr)), "r"((uint32_t)(bytes)) : "memory")
#define MBARRIER_ARRIVE(addr) \
    asm volatile("mbarrier.arrive.shared.b64 _, [%0];" \
        :: "r"((uint32_t)(addr)) : "memory")
#define MBARRIER_WAIT_PARITY(addr, parity) do { \
    uint32_t _m = (uint32_t)(addr); uint32_t _p = (uint32_t)(parity); uint32_t _d; \
    asm volatile("{\n\t.reg .pred p;\n\t" \
        "mbarrier.try_wait.parity.shared.b64 p, [%1], %2;\n\t" \
        "selp.b32 %0, 1, 0, p;\n\t}" : "=r"(_d) : "r"(_m), "r"(_p) : "memory"); \
    if (!_d) { \
        asm volatile("{\n\t.reg .pred P1;\n\tWL_%=:\n\t" \
            "mbarrier.try_wait.parity.shared.b64 P1, [%0], %1, 0x989680;\n\t" \
            "@P1 bra.uni WD_%=;\n\tbra.uni WL_%=;\n\tWD_%=:\n\t}" \
            :: "r"(_m), "r"(_p) : "memory"); \
    } } while (0)

#define TMA_LOAD_3D(smem_addr, tmap, cx, cy, cz, mbar) \
    asm volatile( \
        "cp.async.bulk.tensor.3d.shared::cta.global.tile.mbarrier::complete_tx::bytes " \
        "[%0], [%1, {%2, %3, %4}], [%5];" \
        :: "r"((uint32_t)(smem_addr)), "l"(tmap), \
           "r"((int32_t)(cx)), "r"((int32_t)(cy)), "r"((int32_t)(cz)), \
           "r"((uint32_t)(mbar)) : "memory")

#define LDSM_X4(r0, r1, r2, r3, addr) \
    asm volatile("ldmatrix.sync.aligned.m8n8.x4.shared.b16 {%0,%1,%2,%3}, [%4];" \
        : "=r"(r0), "=r"(r1), "=r"(r2), "=r"(r3) : "r"(addr))

__device__ __forceinline__ void mma_f16(float* d, const uint32_t* a, const uint32_t* b) {
    asm volatile(
        "mma.sync.aligned.m16n8k16.row.col.f32.f16.f16.f32 "
        "{%0,%1,%2,%3}, {%4,%5,%6,%7}, {%8,%9}, {%0,%1,%2,%3};"
        : "+f"(d[0]), "+f"(d[1]), "+f"(d[2]), "+f"(d[3])
        : "r"(a[0]), "r"(a[1]), "r"(a[2]), "r"(a[3]), "r"(b[0]), "r"(b[1]));
}
__device__ __forceinline__ void mma_bf16(float* d, const uint32_t* a, const uint32_t* b) {
    asm volatile(
        "mma.sync.aligned.m16n8k16.row.col.f32.bf16.bf16.f32 "
        "{%0,%1,%2,%3}, {%4,%5,%6,%7}, {%8,%9}, {%0,%1,%2,%3};"
        : "+f"(d[0]), "+f"(d[1]), "+f"(d[2]), "+f"(d[3])
        : "r"(a[0]), "r"(a[1]), "r"(a[2]), "r"(a[3]), "r"(b[0]), "r"(b[1]));
}

// ---------------------------------------------------------------------------
// Prep kernels
// ---------------------------------------------------------------------------
__global__ __launch_bounds__(256) void xT_half_kernel(const float* __restrict__ x)
{
    __shared__ float t[32][33];
    const int b  = blockIdx.z;
    const int n0 = blockIdx.x * 32, c0 = blockIdx.y * 32;
    const int tx = threadIdx.x & 31, ty = threadIdx.x >> 5;
    const float* xb = x + (size_t)b * CC * NN;
    #pragma unroll
    for (int i = 0; i < 32; i += 8)
        t[ty + i][tx] = xb[(size_t)(c0 + ty + i) * NN + n0 + tx];
    __syncthreads();
    __half* o = g_xTh + (size_t)b * NN * CC;
    #pragma unroll
    for (int i = 0; i < 32; i += 8)
        o[(size_t)(n0 + ty + i) * CC + c0 + tx] = __float2half_rn(t[tx][ty + i]);
}

__global__ __launch_bounds__(256) void prep_kernel(
    const float* __restrict__ Wv,
    const float* __restrict__ Wq, const float* __restrict__ bq,
    const float* __restrict__ Wk, const float* __restrict__ bk)
{
    int i = blockIdx.x * 256 + threadIdx.x;
    g_wrh[i] = __float2half_rn(Wv[i]);
    if (i < QK * CC) {
        int r = i >> 9, c = i & 511;
        g_wqkh[i] = __float2half_rn(r < DD ? Wq[(size_t)r * CC + c]
                                           : Wk[(size_t)(r - DD) * CC + c]);
    }
    if (i < QK) g_bqk[i] = (i < DD) ? bq[i] : bk[i - DD];
    if (i < BB * NN) g_rs[i] = 0.0f;
}

// ---------------------------------------------------------------------------
// qk-projection kernel (17 warps): BM=64, BN=128, BK=64, fp16 out.
// ---------------------------------------------------------------------------
constexpr int BN = 128;
constexpr int NSTAGE = 3;
constexpr int B16_BY = BN * 128;

__global__ __launch_bounds__(544)
void qkproj_kernel(const __grid_constant__ CUtensorMap tma_a,
                   const __grid_constant__ CUtensorMap tma_b,
                   const float* __restrict__ bias,
                   __half* __restrict__ outp)
{
    constexpr int A_BY = 64 * 128;
    constexpr int STG  = A_BY + B16_BY;

    __shared__ __align__(8) uint64_t s_bar[2 * NSTAGE];
    extern __shared__ char dsm[];
    const uint32_t dbase = (smem_to_u32(dsm) + 1023) & ~1023u;
    const uint32_t sbar  = smem_to_u32(s_bar);

    const int tid = threadIdx.x, wid = tid >> 5, lid = tid & 31;
    const int mBase = blockIdx.y * 64;
    const int nBase = blockIdx.x * BN;
    const int b     = blockIdx.z;
    const int nchunk = CC / 64;

    if (tid == 0) {
        #pragma unroll
        for (int s = 0; s < NSTAGE; s++) {
            MBARRIER_INIT(sbar + s * 16, 1);
            MBARRIER_INIT(sbar + s * 16 + 8, 16);
        }
    }
    __syncthreads();

    if (tid == 512) {
        int ph = 1, st = 0;
        for (int c = 0; c < nchunk; c++) {
            MBARRIER_WAIT_PARITY(sbar + st * 16 + 8, ph);
            MBARRIER_EXPECT_TX(sbar + st * 16, STG);
            TMA_LOAD_3D(dbase + st * STG,        &tma_a, c * 64, mBase, b, sbar + st * 16);
            TMA_LOAD_3D(dbase + st * STG + A_BY, &tma_b, c * 64, nBase, 0, sbar + st * 16);
            if (++st == NSTAGE) { st = 0; ph ^= 1; }
        }
    }

    if (wid < 16) {
        const int wm = wid & 3, wn = wid >> 2;
        const int mWarp = wm * 16, nWarp = wn * 32;
        const int laneA = lid & 15;
        const int hAu   = (lid >> 4) & 1;
        const int laneB = (lid & 7) + ((lid & 16) ? 8 : 0);
        const int hBu   = (lid >> 3) & 1;
        const int xor7  = lid & 7;

        float cacc[4][4] = {};

        int ph = 0, st = 0;
        for (int c = 0; c < nchunk; c++) {
            MBARRIER_WAIT_PARITY(sbar + st * 16, ph);
            const uint32_t Ab = dbase + st * STG;
            const uint32_t Bb = Ab + A_BY;
            const uint32_t aRowAddr = Ab + (mWarp + laneA) * 128;
            const uint32_t bRowAddr = Bb + (nWarp + laneB) * 128;

            #pragma unroll
            for (int ks = 0; ks < 4; ks++) {
                uint32_t af[4];
                uint32_t bf[4][2];
                const uint32_t cA = (uint32_t)(((2 * ks + hAu) ^ xor7) << 4);
                const uint32_t cB = (uint32_t)(((2 * ks + hBu) ^ xor7) << 4);
                LDSM_X4(af[0], af[1], af[2], af[3], aRowAddr + cA);
                #pragma unroll
                for (int p = 0; p < 2; p++) {
                    uint32_t r0, r1, r2, r3;
                    LDSM_X4(r0, r1, r2, r3, bRowAddr + p * (16 * 128) + cB);
                    bf[2*p][0] = r0; bf[2*p][1] = r1;
                    bf[2*p+1][0] = r2; bf[2*p+1][1] = r3;
                }
                #pragma unroll
                for (int nt = 0; nt < 4; nt++)
                    mma_f16(cacc[nt], af, bf[nt]);
            }
            if (lid == 0) MBARRIER_ARRIVE(sbar + st * 16 + 8);
            if (++st == NSTAGE) { st = 0; ph ^= 1; }
        }

        const int g = lid >> 2, t4 = lid & 3;
        const int r0 = mBase + mWarp + g;
        const int r1 = r0 + 8;
        __half* ob = outp + (size_t)b * NN * QK;
        #pragma unroll
        for (int nt = 0; nt < 4; nt++) {
            const int col = nBase + nWarp + nt * 8 + t4 * 2;
            const float bc0 = bias[col], bc1 = bias[col + 1];
            *(__half2*)&ob[(size_t)r0 * QK + col] =
                __floats2half2_rn(cacc[nt][0] + bc0, cacc[nt][1] + bc1);
            *(__half2*)&ob[(size_t)r1 * QK + col] =
                __floats2half2_rn(cacc[nt][2] + bc0, cacc[nt][3] + bc1);
        }
    }
}

// ---------------------------------------------------------------------------
// MERGED scores + v-proj kernel (8 compute warps + 1 producer, 128x128x64):
// grid (32, 36, BB): y<32 -> scores tile (i=y*128, j=x*128), K=64,
//                    y>=32 -> vproj tile (c=(y-32)*128, n=x*128), K=512.
// scores: bf16 e = exp(q·k), fp32 rowsum atomics.
// vproj:  bf16 v = Wv·xT^T + bias[row].
// ---------------------------------------------------------------------------
constexpr int G8_A_BY = 128 * 128;                // 16 KB
constexpr int G8_STG  = G8_A_BY + B16_BY;         // 32 KB
constexpr int G8_DSMEM = NSTAGE * G8_STG + 1024;

__global__ __launch_bounds__(288)
void sv_kernel(const __grid_constant__ CUtensorMap tmQa,
               const __grid_constant__ CUtensorMap tmQb,
               const __grid_constant__ CUtensorMap tmWV,
               const __grid_constant__ CUtensorMap tmXT,
               const float* __restrict__ bv,
               float* __restrict__ rs,
               __nv_bfloat16* __restrict__ out_e,
               __nv_bfloat16* __restrict__ out_v)
{
    __shared__ __align__(8) uint64_t s_bar[2 * NSTAGE];
    extern __shared__ char dsm[];
    const uint32_t dbase = (smem_to_u32(dsm) + 1023) & ~1023u;
    const uint32_t sbar  = smem_to_u32(s_bar);

    const int tid = threadIdx.x, wid = tid >> 5, lid = tid & 31;
    const int b = blockIdx.z;
    const bool vrole = (blockIdx.y >= 32);
    const int mBase = (vrole ? (blockIdx.y - 32) : blockIdx.y) * 128;
    const int nBase = blockIdx.x * BN;
    const int nchunk = vrole ? (CC / 64) : 1;

    if (tid == 0) {
        #pragma unroll
        for (int s = 0; s < NSTAGE; s++) {
            MBARRIER_INIT(sbar + s * 16, 1);
            MBARRIER_INIT(sbar + s * 16 + 8, 8);
        }
    }
    __syncthreads();

    if (tid == 256) {
        int ph = 1, st = 0;
        for (int c = 0; c < nchunk; c++) {
            MBARRIER_WAIT_PARITY(sbar + st * 16 + 8, ph);
            MBARRIER_EXPECT_TX(sbar + st * 16, G8_STG);
            if (vrole) {
                TMA_LOAD_3D(dbase + st * G8_STG,           &tmWV, c * 64, mBase, 0, sbar + st * 16);
                TMA_LOAD_3D(dbase + st * G8_STG + G8_A_BY, &tmXT, c * 64, nBase, b, sbar + st * 16);
            } else {
                TMA_LOAD_3D(dbase + st * G8_STG,           &tmQa, 0,  mBase, b, sbar + st * 16);
                TMA_LOAD_3D(dbase + st * G8_STG + G8_A_BY, &tmQb, DD, nBase, b, sbar + st * 16);
            }
            if (++st == NSTAGE) { st = 0; ph ^= 1; }
        }
    }

    if (wid < 8) {
        const int wm = wid & 1, wn = wid >> 1;
        const int mWarp = wm * 64, nWarp = wn * 32;
        const int laneA = lid & 15;
        const int hAu   = (lid >> 4) & 1;
        const int laneB = (lid & 7) + ((lid & 16) ? 8 : 0);
        const int hBu   = (lid >> 3) & 1;
        const int xor7  = lid & 7;

        float cacc[4][4][4] = {};

        int ph = 0, st = 0;
        for (int c = 0; c < nchunk; c++) {
            MBARRIER_WAIT_PARITY(sbar + st * 16, ph);
            const uint32_t Ab = dbase + st * G8_STG;
            const uint32_t Bb = Ab + G8_A_BY;
            const uint32_t aRowAddr = Ab + (mWarp + laneA) * 128;
            const uint32_t bRowAddr = Bb + (nWarp + laneB) * 128;

            #pragma unroll
            for (int ks = 0; ks < 4; ks++) {
                uint32_t af[4][4];
                uint32_t bf[4][2];
                const uint32_t cA = (uint32_t)(((2 * ks + hAu) ^ xor7) << 4);
                const uint32_t cB = (uint32_t)(((2 * ks + hBu) ^ xor7) << 4);
                #pragma unroll
                for (int mt = 0; mt < 4; mt++)
                    LDSM_X4(af[mt][0], af[mt][1], af[mt][2], af[mt][3],
                            aRowAddr + mt * (16 * 128) + cA);
                #pragma unroll
                for (int p = 0; p < 2; p++) {
                    uint32_t r0, r1, r2, r3;
                    LDSM_X4(r0, r1, r2, r3, bRowAddr + p * (16 * 128) + cB);
                    bf[2*p][0] = r0; bf[2*p][1] = r1;
                    bf[2*p+1][0] = r2; bf[2*p+1][1] = r3;
                }
                #pragma unroll
                for (int mt = 0; mt < 4; mt++)
                    #pragma unroll
                    for (int nt = 0; nt < 4; nt++)
                        mma_f16(cacc[mt][nt], af[mt], bf[nt]);
            }
            if (lid == 0) MBARRIER_ARRIVE(sbar + st * 16 + 8);
            if (++st == NSTAGE) { st = 0; ph ^= 1; }
        }

        // ---- epilogue ----
        const int g = lid >> 2, t4 = lid & 3;
        float* rs_b = rs + (size_t)b * NN;

        if (vrole) {
            __nv_bfloat16* ob = out_v + (size_t)b * CC * NN;
            #pragma unroll
            for (int mt = 0; mt < 4; mt++) {
                const int r0 = mBase + mWarp + mt * 16 + g;
                const int r1 = r0 + 8;
                const float bias0 = bv[r0], bias1 = bv[r1];
                #pragma unroll
                for (int nt = 0; nt < 4; nt++) {
                    const int col = nBase + nWarp + nt * 8 + t4 * 2;
                    *(__nv_bfloat162*)&ob[(size_t)r0 * NN + col] =
                        __floats2bfloat162_rn(cacc[mt][nt][0] + bias0,
                                              cacc[mt][nt][1] + bias0);
                    *(__nv_bfloat162*)&ob[(size_t)r1 * NN + col] =
                        __floats2bfloat162_rn(cacc[mt][nt][2] + bias1,
                                              cacc[mt][nt][3] + bias1);
                }
            }
        } else {
            __nv_bfloat16* ob = out_e + (size_t)b * NN * NN;
            #pragma unroll
            for (int mt = 0; mt < 4; mt++) {
                const int r0 = mBase + mWarp + mt * 16 + g;
                const int r1 = r0 + 8;
                float s0 = 0.f, s1 = 0.f;
                #pragma unroll
                for (int nt = 0; nt < 4; nt++) {
                    const int col = nBase + nWarp + nt * 8 + t4 * 2;
                    const float v00 = __expf(cacc[mt][nt][0]);
                    const float v01 = __expf(cacc[mt][nt][1]);
                    const float v10 = __expf(cacc[mt][nt][2]);
                    const float v11 = __expf(cacc[mt][nt][3]);
                    s0 += v00 + v01; s1 += v10 + v11;
                    *(__nv_bfloat162*)&ob[(size_t)r0 * NN + col] =
                        __floats2bfloat162_rn(v00, v01);
                    *(__nv_bfloat162*)&ob[(size_t)r1 * NN + col] =
                        __floats2bfloat162_rn(v10, v11);
                }
                s0 += __shfl_xor_sync(0xFFFFFFFFu, s0, 1);
                s0 += __shfl_xor_sync(0xFFFFFFFFu, s0, 2);
                s1 += __shfl_xor_sync(0xFFFFFFFFu, s1, 1);
                s1 += __shfl_xor_sync(0xFFFFFFFFu, s1, 2);
                if (t4 == 0) {
                    atomicAdd(&rs_b[r0], s0);
                    atomicAdd(&rs_b[r1], s1);
                }
            }
        }
    }
}

// ---------------------------------------------------------------------------
// AV (8 warps + producer, bf16 mma): out = gamma*(v·e^T)/rs + x
// ---------------------------------------------------------------------------
__global__ __launch_bounds__(288)
void av8w_kernel(const __grid_constant__ CUtensorMap tma_v,
                 const __grid_constant__ CUtensorMap tma_e,
                 const float* __restrict__ x,
                 const float* __restrict__ rs,
                 const float* __restrict__ gamma,
                 float* __restrict__ outp)
{
    __shared__ __align__(8) uint64_t s_bar[2 * NSTAGE];
    extern __shared__ char dsm[];
    const uint32_t dbase = (smem_to_u32(dsm) + 1023) & ~1023u;
    const uint32_t sbar  = smem_to_u32(s_bar);

    const int tid = threadIdx.x, wid = tid >> 5, lid = tid & 31;
    const int mBase = blockIdx.x * 128;     // c (fastest -> e-tile L2 sharing)
    const int nBase = blockIdx.y * 128;     // i
    const int b     = blockIdx.z;
    const int nchunk = NN / 64;

    if (tid == 0) {
        #pragma unroll
        for (int s = 0; s < NSTAGE; s++) {
            MBARRIER_INIT(sbar + s * 16, 1);
            MBARRIER_INIT(sbar + s * 16 + 8, 8);
        }
    }
    __syncthreads();

    if (tid == 256) {
        int ph = 1, st = 0;
        for (int c = 0; c < nchunk; c++) {
            MBARRIER_WAIT_PARITY(sbar + st * 16 + 8, ph);
            MBARRIER_EXPECT_TX(sbar + st * 16, G8_STG);
            TMA_LOAD_3D(dbase + st * G8_STG,           &tma_v, c * 64, mBase, b, sbar + st * 16);
            TMA_LOAD_3D(dbase + st * G8_STG + G8_A_BY, &tma_e, c * 64, nBase, b, sbar + st * 16);
            if (++st == NSTAGE) { st = 0; ph ^= 1; }
        }
    }

    if (wid < 8) {
        const int wm = wid & 1, wn = wid >> 1;
        const int mWarp = wm * 64, nWarp = wn * 32;
        const int laneA = lid & 15;
        const int hAu   = (lid >> 4) & 1;
        const int laneB = (lid & 7) + ((lid & 16) ? 8 : 0);
        const int hBu   = (lid >> 3) & 1;
        const int xor7  = lid & 7;

        float cacc[4][4][4] = {};

        int ph = 0, st = 0;
        for (int c = 0; c < nchunk; c++) {
            MBARRIER_WAIT_PARITY(sbar + st * 16, ph);
            const uint32_t Ab = dbase + st * G8_STG;
            const uint32_t Bb = Ab + G8_A_BY;
            const uint32_t aRowAddr = Ab + (mWarp + laneA) * 128;
            const uint32_t bRowAddr = Bb + (nWarp + laneB) * 128;

            #pragma unroll
            for (int ks = 0; ks < 4; ks++) {
                uint32_t af[4][4];
                uint32_t bf[4][2];
                const uint32_t cA = (uint32_t)(((2 * ks + hAu) ^ xor7) << 4);
                const uint32_t cB = (uint32_t)(((2 * ks + hBu) ^ xor7) << 4);
                #pragma unroll
                for (int mt = 0; mt < 4; mt++)
                    LDSM_X4(af[mt][0], af[mt][1], af[mt][2], af[mt][3],
                            aRowAddr + mt * (16 * 128) + cA);
                #pragma unroll
                for (int p = 0; p < 2; p++) {
                    uint32_t r0, r1, r2, r3;
                    LDSM_X4(r0, r1, r2, r3, bRowAddr + p * (16 * 128) + cB);
                    bf[2*p][0] = r0; bf[2*p][1] = r1;
                    bf[2*p+1][0] = r2; bf[2*p+1][1] = r3;
                }
                #pragma unroll
                for (int mt = 0; mt < 4; mt++)
                    #pragma unroll
                    for (int nt = 0; nt < 4; nt++)
                        mma_bf16(cacc[mt][nt], af[mt], bf[nt]);
            }
            if (lid == 0) MBARRIER_ARRIVE(sbar + st * 16 + 8);
            if (++st == NSTAGE) { st = 0; ph ^= 1; }
        }

        const int g = lid >> 2, t4 = lid & 3;
        const float gm = gamma[0];
        const float* rs_b = rs + (size_t)b * NN;
        const float* xb = x + (size_t)b * CC * NN;
        float* ob = outp + (size_t)b * CC * NN;

        #pragma unroll
        for (int mt = 0; mt < 4; mt++) {
            const int r0 = mBase + mWarp + mt * 16 + g;
            const int r1 = r0 + 8;
            #pragma unroll
            for (int nt = 0; nt < 4; nt++) {
                const int col = nBase + nWarp + nt * 8 + t4 * 2;
                const float i0 = __fdividef(1.0f, rs_b[col]);
                const float i1 = __fdividef(1.0f, rs_b[col + 1]);
                const float2 x0 = *(const float2*)&xb[(size_t)r0 * NN + col];
                const float2 x1 = *(const float2*)&xb[(size_t)r1 * NN + col];
                *(float2*)&ob[(size_t)r0 * NN + col] =
                    make_float2(gm * cacc[mt][nt][0] * i0 + x0.x,
                                gm * cacc[mt][nt][1] * i1 + x0.y);
                *(float2*)&ob[(size_t)r1 * NN + col] =
                    make_float2(gm * cacc[mt][nt][2] * i0 + x1.x,
                                gm * cacc[mt][nt][3] * i1 + x1.y);
            }
        }
    }
}

// ---------------------------------------------------------------------------
// Host side
// ---------------------------------------------------------------------------
typedef CUresult (*EncodeFn)(CUtensorMap*, CUtensorMapDataType, cuuint32_t, void*,
                             const cuuint64_t*, const cuuint64_t*, const cuuint32_t*,
                             const cuuint32_t*, CUtensorMapInterleave, CUtensorMapSwizzle,
                             CUtensorMapL2promotion, CUtensorMapFloatOOBfill);

static void build_tm(EncodeFn enc, CUtensorMap* tm, void* ptr,
                     uint64_t d0, uint64_t d1, uint64_t d2,
                     uint64_t s1b, uint64_t s2b, uint32_t b0, uint32_t b1)
{
    cuuint64_t dims[3] = {d0, d1, d2};
    cuuint64_t str[2]  = {s1b, s2b};
    cuuint32_t box[3]  = {b0, b1, 1};
    cuuint32_t es[3]   = {1, 1, 1};
    enc(tm, CU_TENSOR_MAP_DATA_TYPE_UINT16, 3, ptr, dims, str, box, es,
        CU_TENSOR_MAP_INTERLEAVE_NONE, CU_TENSOR_MAP_SWIZZLE_128B,
        CU_TENSOR_MAP_L2_PROMOTION_L2_128B, CU_TENSOR_MAP_FLOAT_OOB_FILL_NONE);
}

extern "C" void kernel_launch(void* const* d_in, const int* in_sizes, int n_in,
                              void* d_out, int out_size)
{
    (void)in_sizes; (void)n_in; (void)out_size;
    const float* x     = (const float*)d_in[0];
    const float* Wq    = (const float*)d_in[1];
    const float* bq    = (const float*)d_in[2];
    const float* Wk    = (const float*)d_in[3];
    const float* bk    = (const float*)d_in[4];
    const float* Wv    = (const float*)d_in[5];
    const float* bv    = (const float*)d_in[6];
    const float* gamma = (const float*)d_in[7];
    float* out = (float*)d_out;

    EncodeFn enc = nullptr;
    cudaDriverEntryPointQueryResult qr;
    cudaGetDriverEntryPointByVersion("cuTensorMapEncodeTiled", (void**)&enc, 12000,
                                     cudaEnableDefault, &qr);

    void *pqk, *pvb, *peb, *pxT, *pwr, *pwqk, *pbqk, *prs;
    cudaGetSymbolAddress(&pqk,  g_qkh);
    cudaGetSymbolAddress(&pvb,  g_vb);
    cudaGetSymbolAddress(&peb,  g_eb);
    cudaGetSymbolAddress(&pxT,  g_xTh);
    cudaGetSymbolAddress(&pwr,  g_wrh);
    cudaGetSymbolAddress(&pwqk, g_wqkh);
    cudaGetSymbolAddress(&pbqk, g_bqk);
    cudaGetSymbolAddress(&prs,  g_rs);

    CUtensorMap tmXT_A64, tmXT_B, tmWQK, tmWV, tmQKa, tmQKb, tmVb, tmEb;
    build_tm(enc, &tmXT_A64, pxT, CC, NN, BB, (uint64_t)CC * 2, (uint64_t)NN * CC * 2, 64, 64);
    build_tm(enc, &tmXT_B,   pxT, CC, NN, BB, (uint64_t)CC * 2, (uint64_t)NN * CC * 2, 64, 128);
    build_tm(enc, &tmWQK, pwqk, CC, QK, 1, (uint64_t)CC * 2, (uint64_t)QK * CC * 2, 64, 128);
    build_tm(enc, &tmWV,  pwr,  CC, CC, 1, (uint64_t)CC * 2, (uint64_t)CC * CC * 2, 64, 128);
    build_tm(enc, &tmQKa, pqk, QK, NN, BB, (uint64_t)QK * 2, (uint64_t)NN * QK * 2, 64, 128);
    build_tm(enc, &tmQKb, pqk, QK, NN, BB, (uint64_t)QK * 2, (uint64_t)NN * QK * 2, 64, 128);
    build_tm(enc, &tmVb, pvb, NN, CC, BB, (uint64_t)NN * 2, (uint64_t)CC * NN * 2, 64, 128);
    build_tm(enc, &tmEb, peb, NN, NN, BB, (uint64_t)NN * 2, (uint64_t)NN * NN * 2, 64, 128);

    constexpr int DS1 = NSTAGE * (64 * 128 + B16_BY) + 1024;
    cudaFuncSetAttribute(qkproj_kernel, cudaFuncAttributeMaxDynamicSharedMemorySize, DS1);
    cudaFuncSetAttribute(sv_kernel, cudaFuncAttributeMaxDynamicSharedMemorySize, G8_DSMEM);
    cudaFuncSetAttribute(av8w_kernel, cudaFuncAttributeMaxDynamicSharedMemorySize, G8_DSMEM);

    float* frs = (float*)prs;

    // 1. prep
    xT_half_kernel<<<dim3(NN / 32, CC / 32, BB), 256>>>(x);
    prep_kernel<<<(CC * CC) / 256, 256>>>(Wv, Wq, bq, Wk, bk);
    // 2. qk projection: 128 CTAs, K=512, fp16 out
    qkproj_kernel<<<dim3(1, NN / 64, BB), 544, DS1>>>(
        tmXT_A64, tmWQK, (const float*)pbqk, (__half*)pqk);
    // 3. MERGED scores + v-proj: one launch, 2304 CTAs
    sv_kernel<<<dim3(32, 36, BB), 288, G8_DSMEM>>>(
        tmQKa, tmQKb, tmWV, tmXT_B, bv, frs,
        (__nv_bfloat16*)peb, (__nv_bfloat16*)pvb);
    // 4. AV (bf16 mma): out = gamma*(v·e^T)/rs + x, K=4096
    av8w_kernel<<<dim3(CC / 128, NN / 128, BB), 288, G8_DSMEM>>>(
        tmVb, tmEb, x, frs, gamma, out);
}

// round 15
// speedup vs baseline: 1.0359x; 1.0359x over previous
#include <cuda_runtime.h>
#include <cuda.h>
#include <cuda_fp16.h>
#include <cuda_bf16.h>
#include <cstdint>
#include <math.h>

constexpr int BB = 2;
constexpr int CC = 512;
constexpr int NN = 4096;
constexpr int DD = 64;
constexpr int QK = 128;

// ---------------------------------------------------------------------------
// Scratch
// ---------------------------------------------------------------------------
__device__ __align__(1024) __half         g_qkh[(size_t)BB * NN * QK]; // fp16 q|k
__device__ __align__(1024) __nv_bfloat16  g_vb [(size_t)BB * CC * NN]; // bf16 v
__device__ __align__(1024) __half         g_xTh[(size_t)BB * NN * CC]; // fp16 xT
__device__ __align__(1024) __half         g_wrh[(size_t)CC * CC];      // fp16 Wv
__device__ __align__(1024) __half         g_wqkh[(size_t)QK * CC];     // fp16 Wq|Wk
__device__ __align__(1024) float          g_bqk[QK];
__device__ __align__(1024) __nv_bfloat16  g_eb [(size_t)BB * NN * NN]; // bf16 exp(s)
__device__ __align__(1024) float          g_rs [(size_t)BB * NN];      // fp32 row sums

// ---------------------------------------------------------------------------
// Helpers
// ---------------------------------------------------------------------------
__device__ __forceinline__ uint32_t smem_to_u32(const void* p) {
    uint32_t a;
    asm("{ .reg .u64 t; cvta.to.shared.u64 t, %1; cvt.u32.u64 %0, t; }"
        : "=r"(a) : "l"(p));
    return a;
}

#define MBARRIER_INIT(addr, cnt) \
    asm volatile("mbarrier.init.shared.b64 [%0], %1;" \
        :: "r"((uint32_t)(addr)), "r"((uint32_t)(cnt)) : "memory")
#define MBARRIER_EXPECT_TX(addr, bytes) \
    asm volatile("mbarrier.arrive.expect_tx.shared.b64 _, [%0], %1;" \
        :: "r"((uint32_t)(addr)), "r"((uint32_t)(bytes)) : "memory")
#define MBARRIER_ARRIVE(addr) \
    asm volatile("mbarrier.arrive.shared.b64 _, [%0];" \
        :: "r"((uint32_t)(addr)) : "memory")
#define MBARRIER_WAIT_PARITY(addr, parity) do { \
    uint32_t _m = (uint32_t)(addr); uint32_t _p = (uint32_t)(parity); uint32_t _d; \
    asm volatile("{\n\t.reg .pred p;\n\t" \
        "mbarrier.try_wait.parity.shared.b64 p, [%1], %2;\n\t" \
        "selp.b32 %0, 1, 0, p;\n\t}" : "=r"(_d) : "r"(_m), "r"(_p) : "memory"); \
    if (!_d) { \
        asm volatile("{\n\t.reg .pred P1;\n\tWL_%=:\n\t" \
            "mbarrier.try_wait.parity.shared.b64 P1, [%0], %1, 0x989680;\n\t" \
            "@P1 bra.uni WD_%=;\n\tbra.uni WL_%=;\n\tWD_%=:\n\t}" \
            :: "r"(_m), "r"(_p) : "memory"); \
    } } while (0)

#define TMA_LOAD_3D(smem_addr, tmap, cx, cy, cz, mbar) \
    asm volatile( \
        "cp.async.bulk.tensor.3d.shared::cta.global.tile.mbarrier::complete_tx::bytes " \
        "[%0], [%1, {%2, %3, %4}], [%5];" \
        :: "r"((uint32_t)(smem_addr)), "l"(tmap), \
           "r"((int32_t)(cx)), "r"((int32_t)(cy)), "r"((int32_t)(cz)), \
           "r"((uint32_t)(mbar)) : "memory")

#define LDSM_X4(r0, r1, r2, r3, addr) \
    asm volatile("ldmatrix.sync.aligned.m8n8.x4.shared.b16 {%0,%1,%2,%3}, [%4];" \
        : "=r"(r0), "=r"(r1), "=r"(r2), "=r"(r3) : "r"(addr))

__device__ __forceinline__ void mma_f16(float* d, const uint32_t* a, const uint32_t* b) {
    asm volatile(
        "mma.sync.aligned.m16n8k16.row.col.f32.f16.f16.f32 "
        "{%0,%1,%2,%3}, {%4,%5,%6,%7}, {%8,%9}, {%0,%1,%2,%3};"
        : "+f"(d[0]), "+f"(d[1]), "+f"(d[2]), "+f"(d[3])
        : "r"(a[0]), "r"(a[1]), "r"(a[2]), "r"(a[3]), "r"(b[0]), "r"(b[1]));
}
__device__ __forceinline__ void mma_bf16(float* d, const uint32_t* a, const uint32_t* b) {
    asm volatile(
        "mma.sync.aligned.m16n8k16.row.col.f32.bf16.bf16.f32 "
        "{%0,%1,%2,%3}, {%4,%5,%6,%7}, {%8,%9}, {%0,%1,%2,%3};"
        : "+f"(d[0]), "+f"(d[1]), "+f"(d[2]), "+f"(d[3])
        : "r"(a[0]), "r"(a[1]), "r"(a[2]), "r"(a[3]), "r"(b[0]), "r"(b[1]));
}

// ---------------------------------------------------------------------------
// Fused prep: xT transpose+fp16 (all CTAs) + weight prep (first 1024 CTAs)
// grid (128, 16, 2) x 256 threads
// ---------------------------------------------------------------------------
__global__ __launch_bounds__(256) void fusedprep_kernel(
    const float* __restrict__ x,
    const float* __restrict__ Wv,
    const float* __restrict__ Wq, const float* __restrict__ bq,
    const float* __restrict__ Wk, const float* __restrict__ bk)
{
    __shared__ float t[32][33];
    const int b  = blockIdx.z;
    const int n0 = blockIdx.x * 32, c0 = blockIdx.y * 32;
    const int tx = threadIdx.x & 31, ty = threadIdx.x >> 5;
    const float* xb = x + (size_t)b * CC * NN;
    #pragma unroll
    for (int i = 0; i < 32; i += 8)
        t[ty + i][tx] = xb[(size_t)(c0 + ty + i) * NN + n0 + tx];

    // weight prep on first 1024 linear CTAs (no dependence on smem)
    const int bid = (blockIdx.z * 16 + blockIdx.y) * 128 + blockIdx.x;
    if (bid < 1024) {
        int i = bid * 256 + threadIdx.x;        // over CC*CC
        g_wrh[i] = __float2half_rn(Wv[i]);
        if (i < QK * CC) {
            int r = i >> 9, c = i & 511;
            g_wqkh[i] = __float2half_rn(r < DD ? Wq[(size_t)r * CC + c]
                                               : Wk[(size_t)(r - DD) * CC + c]);
        }
        if (i < QK) g_bqk[i] = (i < DD) ? bq[i] : bk[i - DD];
        if (i < BB * NN) g_rs[i] = 0.0f;
    }

    __syncthreads();
    __half* o = g_xTh + (size_t)b * NN * CC;
    #pragma unroll
    for (int i = 0; i < 32; i += 8)
        o[(size_t)(n0 + ty + i) * CC + c0 + tx] = __float2half_rn(t[tx][ty + i]);
}

// ---------------------------------------------------------------------------
// qk-projection kernel (17 warps): BM=64, BN=128, BK=64, fp16 out.
// ---------------------------------------------------------------------------
constexpr int BN = 128;
constexpr int NSTAGE = 3;
constexpr int B16_BY = BN * 128;

__global__ __launch_bounds__(544)
void qkproj_kernel(const __grid_constant__ CUtensorMap tma_a,
                   const __grid_constant__ CUtensorMap tma_b,
                   const float* __restrict__ bias,
                   __half* __restrict__ outp)
{
    constexpr int A_BY = 64 * 128;
    constexpr int STG  = A_BY + B16_BY;

    __shared__ __align__(8) uint64_t s_bar[2 * NSTAGE];
    extern __shared__ char dsm[];
    const uint32_t dbase = (smem_to_u32(dsm) + 1023) & ~1023u;
    const uint32_t sbar  = smem_to_u32(s_bar);

    const int tid = threadIdx.x, wid = tid >> 5, lid = tid & 31;
    const int mBase = blockIdx.y * 64;
    const int nBase = blockIdx.x * BN;
    const int b     = blockIdx.z;
    const int nchunk = CC / 64;

    if (tid == 0) {
        #pragma unroll
        for (int s = 0; s < NSTAGE; s++) {
            MBARRIER_INIT(sbar + s * 16, 1);
            MBARRIER_INIT(sbar + s * 16 + 8, 16);
        }
    }
    __syncthreads();

    if (tid == 512) {
        int ph = 1, st = 0;
        for (int c = 0; c < nchunk; c++) {
            MBARRIER_WAIT_PARITY(sbar + st * 16 + 8, ph);
            MBARRIER_EXPECT_TX(sbar + st * 16, STG);
            TMA_LOAD_3D(dbase + st * STG,        &tma_a, c * 64, mBase, b, sbar + st * 16);
            TMA_LOAD_3D(dbase + st * STG + A_BY, &tma_b, c * 64, nBase, 0, sbar + st * 16);
            if (++st == NSTAGE) { st = 0; ph ^= 1; }
        }
    }

    if (wid < 16) {
        const int wm = wid & 3, wn = wid >> 2;
        const int mWarp = wm * 16, nWarp = wn * 32;
        const int laneA = lid & 15;
        const int hAu   = (lid >> 4) & 1;
        const int laneB = (lid & 7) + ((lid & 16) ? 8 : 0);
        const int hBu   = (lid >> 3) & 1;
        const int xor7  = lid & 7;

        float cacc[4][4] = {};

        int ph = 0, st = 0;
        for (int c = 0; c < nchunk; c++) {
            MBARRIER_WAIT_PARITY(sbar + st * 16, ph);
            const uint32_t Ab = dbase + st * STG;
            const uint32_t Bb = Ab + A_BY;
            const uint32_t aRowAddr = Ab + (mWarp + laneA) * 128;
            const uint32_t bRowAddr = Bb + (nWarp + laneB) * 128;

            #pragma unroll
            for (int ks = 0; ks < 4; ks++) {
                uint32_t af[4];
                uint32_t bf[4][2];
                const uint32_t cA = (uint32_t)(((2 * ks + hAu) ^ xor7) << 4);
                const uint32_t cB = (uint32_t)(((2 * ks + hBu) ^ xor7) << 4);
                LDSM_X4(af[0], af[1], af[2], af[3], aRowAddr + cA);
                #pragma unroll
                for (int p = 0; p < 2; p++) {
                    uint32_t r0, r1, r2, r3;
                    LDSM_X4(r0, r1, r2, r3, bRowAddr + p * (16 * 128) + cB);
                    bf[2*p][0] = r0; bf[2*p][1] = r1;
                    bf[2*p+1][0] = r2; bf[2*p+1][1] = r3;
                }
                #pragma unroll
                for (int nt = 0; nt < 4; nt++)
                    mma_f16(cacc[nt], af, bf[nt]);
            }
            if (lid == 0) MBARRIER_ARRIVE(sbar + st * 16 + 8);
            if (++st == NSTAGE) { st = 0; ph ^= 1; }
        }

        const int g = lid >> 2, t4 = lid & 3;
        const int r0 = mBase + mWarp + g;
        const int r1 = r0 + 8;
        __half* ob = outp + (size_t)b * NN * QK;
        #pragma unroll
        for (int nt = 0; nt < 4; nt++) {
            const int col = nBase + nWarp + nt * 8 + t4 * 2;
            const float bc0 = bias[col], bc1 = bias[col + 1];
            *(__half2*)&ob[(size_t)r0 * QK + col] =
                __floats2half2_rn(cacc[nt][0] + bc0, cacc[nt][1] + bc1);
            *(__half2*)&ob[(size_t)r1 * QK + col] =
                __floats2half2_rn(cacc[nt][2] + bc0, cacc[nt][3] + bc1);
        }
    }
}

// ---------------------------------------------------------------------------
// 4 compute warps (64x64 warp tile) + 1 producer: CTA tile 128x128x64.
// Halves LDSM bytes per mma vs 64x32 tiles (crossbar was the binding pipe).
// mode 0: bf16 out = C + bias[row]      (v-proj, fp16 mma)
// mode 1: fp32 out = gamma*C/rs[col]+x  (AV, bf16 mma)
// mode 2: bf16 out = exp(C); rs atomics (scores, fp16 mma)
// ---------------------------------------------------------------------------
constexpr int G4_A_BY = 128 * 128;                // 16 KB
constexpr int G4_STG  = G4_A_BY + B16_BY;         // 32 KB
constexpr int G4_DSMEM = NSTAGE * G4_STG + 1024;

template<int USE_BF16>
__global__ __launch_bounds__(160, 2)
void gemm4w_kernel(const __grid_constant__ CUtensorMap tma_a,
                   const __grid_constant__ CUtensorMap tma_b,
                   int k_total, int mode, int a_batched, int b_batched,
                   int a_koff, int b_koff, int swap_xy,
                   const float* __restrict__ aux,     // mode0: bias, mode1: x
                   float* __restrict__ rs,
                   const float* __restrict__ gamma,
                   void* __restrict__ outp, size_t out_bstride, int out_rstride)
{
    __shared__ __align__(8) uint64_t s_bar[2 * NSTAGE];
    extern __shared__ char dsm[];
    const uint32_t dbase = (smem_to_u32(dsm) + 1023) & ~1023u;
    const uint32_t sbar  = smem_to_u32(s_bar);

    const int tid = threadIdx.x, wid = tid >> 5, lid = tid & 31;
    const int mBase = (swap_xy ? blockIdx.x : blockIdx.y) * 128;
    const int nBase = (swap_xy ? blockIdx.y : blockIdx.x) * 128;
    const int b     = blockIdx.z;
    const int nchunk = k_total / 64;

    if (tid == 0) {
        #pragma unroll
        for (int s = 0; s < NSTAGE; s++) {
            MBARRIER_INIT(sbar + s * 16, 1);
            MBARRIER_INIT(sbar + s * 16 + 8, 4);
        }
    }
    __syncthreads();

    if (tid == 128) {
        const int az = a_batched ? b : 0;
        const int bz = b_batched ? b : 0;
        int ph = 1, st = 0;
        for (int c = 0; c < nchunk; c++) {
            MBARRIER_WAIT_PARITY(sbar + st * 16 + 8, ph);
            MBARRIER_EXPECT_TX(sbar + st * 16, G4_STG);
            TMA_LOAD_3D(dbase + st * G4_STG,           &tma_a, a_koff + c * 64, mBase, az, sbar + st * 16);
            TMA_LOAD_3D(dbase + st * G4_STG + G4_A_BY, &tma_b, b_koff + c * 64, nBase, bz, sbar + st * 16);
            if (++st == NSTAGE) { st = 0; ph ^= 1; }
        }
    }

    if (wid < 4) {
        const int wm = wid & 1, wn = wid >> 1;          // 2 x 2 warp grid
        const int mWarp = wm * 64, nWarp = wn * 64;     // 64 x 64 warp tile
        const int laneA = lid & 15;
        const int hAu   = (lid >> 4) & 1;
        const int laneB = (lid & 7) + ((lid & 16) ? 8 : 0);
        const int hBu   = (lid >> 3) & 1;
        const int xor7  = lid & 7;

        float cacc[4][8][4] = {};

        int ph = 0, st = 0;
        for (int c = 0; c < nchunk; c++) {
            MBARRIER_WAIT_PARITY(sbar + st * 16, ph);
            const uint32_t Ab = dbase + st * G4_STG;
            const uint32_t Bb = Ab + G4_A_BY;
            const uint32_t aRowAddr = Ab + (mWarp + laneA) * 128;
            const uint32_t bRowAddr = Bb + (nWarp + laneB) * 128;

            #pragma unroll
            for (int ks = 0; ks < 4; ks++) {
                uint32_t af[4][4];
                uint32_t bf[8][2];
                const uint32_t cA = (uint32_t)(((2 * ks + hAu) ^ xor7) << 4);
                const uint32_t cB = (uint32_t)(((2 * ks + hBu) ^ xor7) << 4);
                #pragma unroll
                for (int mt = 0; mt < 4; mt++)
                    LDSM_X4(af[mt][0], af[mt][1], af[mt][2], af[mt][3],
                            aRowAddr + mt * (16 * 128) + cA);
                #pragma unroll
                for (int p = 0; p < 4; p++) {
                    uint32_t r0, r1, r2, r3;
                    LDSM_X4(r0, r1, r2, r3, bRowAddr + p * (16 * 128) + cB);
                    bf[2*p][0] = r0; bf[2*p][1] = r1;
                    bf[2*p+1][0] = r2; bf[2*p+1][1] = r3;
                }
                #pragma unroll
                for (int mt = 0; mt < 4; mt++)
                    #pragma unroll
                    for (int nt = 0; nt < 8; nt++) {
                        if (USE_BF16) mma_bf16(cacc[mt][nt], af[mt], bf[nt]);
                        else          mma_f16 (cacc[mt][nt], af[mt], bf[nt]);
                    }
            }
            if (lid == 0) MBARRIER_ARRIVE(sbar + st * 16 + 8);
            if (++st == NSTAGE) { st = 0; ph ^= 1; }
        }

        // ---- epilogue ----
        const int g = lid >> 2, t4 = lid & 3;
        float* rs_b = rs + (size_t)b * NN;

        if (mode == 1) {
            const float gm = gamma[0];
            const float* xb = aux + (size_t)b * out_bstride;
            float* ob = (float*)outp + (size_t)b * out_bstride;
            #pragma unroll
            for (int mt = 0; mt < 4; mt++) {
                const int r0 = mBase + mWarp + mt * 16 + g;
                const int r1 = r0 + 8;
                #pragma unroll
                for (int nt = 0; nt < 8; nt++) {
                    const int col = nBase + nWarp + nt * 8 + t4 * 2;
                    const float i0 = __fdividef(1.0f, rs_b[col]);
                    const float i1 = __fdividef(1.0f, rs_b[col + 1]);
                    const float2 x0 = *(const float2*)&xb[(size_t)r0 * out_rstride + col];
                    const float2 x1 = *(const float2*)&xb[(size_t)r1 * out_rstride + col];
                    *(float2*)&ob[(size_t)r0 * out_rstride + col] =
                        make_float2(gm * cacc[mt][nt][0] * i0 + x0.x,
                                    gm * cacc[mt][nt][1] * i1 + x0.y);
                    *(float2*)&ob[(size_t)r1 * out_rstride + col] =
                        make_float2(gm * cacc[mt][nt][2] * i0 + x1.x,
                                    gm * cacc[mt][nt][3] * i1 + x1.y);
                }
            }
        } else {
            __nv_bfloat16* ob = (__nv_bfloat16*)outp + (size_t)b * out_bstride;
            #pragma unroll
            for (int mt = 0; mt < 4; mt++) {
                const int r0 = mBase + mWarp + mt * 16 + g;
                const int r1 = r0 + 8;
                float bias0 = 0.f, bias1 = 0.f;
                if (mode == 0) { bias0 = aux[r0]; bias1 = aux[r1]; }
                float s0 = 0.f, s1 = 0.f;
                #pragma unroll
                for (int nt = 0; nt < 8; nt++) {
                    const int col = nBase + nWarp + nt * 8 + t4 * 2;
                    float v00 = cacc[mt][nt][0], v01 = cacc[mt][nt][1];
                    float v10 = cacc[mt][nt][2], v11 = cacc[mt][nt][3];
                    if (mode == 0) {
                        v00 += bias0; v01 += bias0; v10 += bias1; v11 += bias1;
                    } else {    // mode 2
                        v00 = __expf(v00); v01 = __expf(v01);
                        v10 = __expf(v10); v11 = __expf(v11);
                        s0 += v00 + v01; s1 += v10 + v11;
                    }
                    *(__nv_bfloat162*)&ob[(size_t)r0 * out_rstride + col] =
                        __floats2bfloat162_rn(v00, v01);
                    *(__nv_bfloat162*)&ob[(size_t)r1 * out_rstride + col] =
                        __floats2bfloat162_rn(v10, v11);
                }
                if (mode == 2) {
                    s0 += __shfl_xor_sync(0xFFFFFFFFu, s0, 1);
                    s0 += __shfl_xor_sync(0xFFFFFFFFu, s0, 2);
                    s1 += __shfl_xor_sync(0xFFFFFFFFu, s1, 1);
                    s1 += __shfl_xor_sync(0xFFFFFFFFu, s1, 2);
                    if (t4 == 0) {
                        atomicAdd(&rs_b[r0], s0);
                        atomicAdd(&rs_b[r1], s1);
                    }
                }
            }
        }
    }
}

// ---------------------------------------------------------------------------
// Host side
// ---------------------------------------------------------------------------
typedef CUresult (*EncodeFn)(CUtensorMap*, CUtensorMapDataType, cuuint32_t, void*,
                             const cuuint64_t*, const cuuint64_t*, const cuuint32_t*,
                             const cuuint32_t*, CUtensorMapInterleave, CUtensorMapSwizzle,
                             CUtensorMapL2promotion, CUtensorMapFloatOOBfill);

static void build_tm(EncodeFn enc, CUtensorMap* tm, void* ptr,
                     uint64_t d0, uint64_t d1, uint64_t d2,
                     uint64_t s1b, uint64_t s2b, uint32_t b0, uint32_t b1)
{
    cuuint64_t dims[3] = {d0, d1, d2};
    cuuint64_t str[2]  = {s1b, s2b};
    cuuint32_t box[3]  = {b0, b1, 1};
    cuuint32_t es[3]   = {1, 1, 1};
    enc(tm, CU_TENSOR_MAP_DATA_TYPE_UINT16, 3, ptr, dims, str, box, es,
        CU_TENSOR_MAP_INTERLEAVE_NONE, CU_TENSOR_MAP_SWIZZLE_128B,
        CU_TENSOR_MAP_L2_PROMOTION_L2_128B, CU_TENSOR_MAP_FLOAT_OOB_FILL_NONE);
}

extern "C" void kernel_launch(void* const* d_in, const int* in_sizes, int n_in,
                              void* d_out, int out_size)
{
    (void)in_sizes; (void)n_in; (void)out_size;
    const float* x     = (const float*)d_in[0];
    const float* Wq    = (const float*)d_in[1];
    const float* bq    = (const float*)d_in[2];
    const float* Wk    = (const float*)d_in[3];
    const float* bk    = (const float*)d_in[4];
    const float* Wv    = (const float*)d_in[5];
    const float* bv    = (const float*)d_in[6];
    const float* gamma = (const float*)d_in[7];
    float* out = (float*)d_out;

    EncodeFn enc = nullptr;
    cudaDriverEntryPointQueryResult qr;
    cudaGetDriverEntryPointByVersion("cuTensorMapEncodeTiled", (void**)&enc, 12000,
                                     cudaEnableDefault, &qr);

    void *pqk, *pvb, *peb, *pxT, *pwr, *pwqk, *pbqk, *prs;
    cudaGetSymbolAddress(&pqk,  g_qkh);
    cudaGetSymbolAddress(&pvb,  g_vb);
    cudaGetSymbolAddress(&peb,  g_eb);
    cudaGetSymbolAddress(&pxT,  g_xTh);
    cudaGetSymbolAddress(&pwr,  g_wrh);
    cudaGetSymbolAddress(&pwqk, g_wqkh);
    cudaGetSymbolAddress(&pbqk, g_bqk);
    cudaGetSymbolAddress(&prs,  g_rs);

    CUtensorMap tmXT_A64, tmXT_B, tmWQK, tmWV, tmQKa, tmQKb, tmVb, tmEb;
    build_tm(enc, &tmXT_A64, pxT, CC, NN, BB, (uint64_t)CC * 2, (uint64_t)NN * CC * 2, 64, 64);
    build_tm(enc, &tmXT_B,   pxT, CC, NN, BB, (uint64_t)CC * 2, (uint64_t)NN * CC * 2, 64, 128);
    build_tm(enc, &tmWQK, pwqk, CC, QK, 1, (uint64_t)CC * 2, (uint64_t)QK * CC * 2, 64, 128);
    build_tm(enc, &tmWV,  pwr,  CC, CC, 1, (uint64_t)CC * 2, (uint64_t)CC * CC * 2, 64, 128);
    build_tm(enc, &tmQKa, pqk, QK, NN, BB, (uint64_t)QK * 2, (uint64_t)NN * QK * 2, 64, 128);
    build_tm(enc, &tmQKb, pqk, QK, NN, BB, (uint64_t)QK * 2, (uint64_t)NN * QK * 2, 64, 128);
    build_tm(enc, &tmVb, pvb, NN, CC, BB, (uint64_t)NN * 2, (uint64_t)CC * NN * 2, 64, 128);
    build_tm(enc, &tmEb, peb, NN, NN, BB, (uint64_t)NN * 2, (uint64_t)NN * NN * 2, 64, 128);

    constexpr int DS1 = NSTAGE * (64 * 128 + B16_BY) + 1024;
    cudaFuncSetAttribute(qkproj_kernel, cudaFuncAttributeMaxDynamicSharedMemorySize, DS1);
    cudaFuncSetAttribute(gemm4w_kernel<0>, cudaFuncAttributeMaxDynamicSharedMemorySize, G4_DSMEM);
    cudaFuncSetAttribute(gemm4w_kernel<1>, cudaFuncAttributeMaxDynamicSharedMemorySize, G4_DSMEM);

    float* frs = (float*)prs;

    // 1. fused prep: xT transpose/convert + weight conversion + rs zero
    fusedprep_kernel<<<dim3(NN / 32, CC / 32, BB), 256>>>(x, Wv, Wq, bq, Wk, bk);
    // 2. qk projection: 128 CTAs, K=512, fp16 out
    qkproj_kernel<<<dim3(1, NN / 64, BB), 544, DS1>>>(
        tmXT_A64, tmWQK, (const float*)pbqk, (__half*)pqk);
    // 3. v projection: g_vb[c][n] = bf16(Wv·xT^T + bv), K=512
    gemm4w_kernel<0><<<dim3(NN / 128, CC / 128, BB), 160, G4_DSMEM>>>(
        tmWV, tmXT_B, CC, 0, 0, 1, 0, 0, 0, bv, frs, gamma,
        pvb, (size_t)CC * NN, NN);
    // 4. scores: g_eb[i][j] = bf16(exp(q·k)), fp32 rowsums, K=64
    gemm4w_kernel<0><<<dim3(NN / 128, NN / 128, BB), 160, G4_DSMEM>>>(
        tmQKa, tmQKb, DD, 2, 1, 1, 0, DD, 0, nullptr, frs, gamma,
        peb, (size_t)NN * NN, NN);
    // 5. AV (bf16 mma): out = gamma*(v·e^T)/rs + x, K=4096
    //    c-tiles fastest -> e tile shared in L2
    gemm4w_kernel<1><<<dim3(CC / 128, NN / 128, BB), 160, G4_DSMEM>>>(
        tmVb, tmEb, NN, 1, 1, 1, 0, 0, 1, x, frs, gamma,
        out, (size_t)CC * NN, NN);
}

// round 16
// speedup vs baseline: 1.0529x; 1.0164x over previous
#include <cuda_runtime.h>
#include <cuda.h>
#include <cuda_fp16.h>
#include <cuda_bf16.h>
#include <cstdint>
#include <math.h>

constexpr int BB = 2;
constexpr int CC = 512;
constexpr int NN = 4096;
constexpr int DD = 64;
constexpr int QK = 128;

// ---------------------------------------------------------------------------
// Scratch
// ---------------------------------------------------------------------------
__device__ __align__(1024) __half         g_qkh[(size_t)BB * NN * QK]; // fp16 q|k
__device__ __align__(1024) __nv_bfloat16  g_vb [(size_t)BB * CC * NN]; // bf16 v
__device__ __align__(1024) __half         g_xTh[(size_t)BB * NN * CC]; // fp16 xT
__device__ __align__(1024) __half         g_wrh[(size_t)CC * CC];      // fp16 Wv
__device__ __align__(1024) __half         g_wqkh[(size_t)QK * CC];     // fp16 Wq|Wk
__device__ __align__(1024) float          g_bqk[QK];
__device__ __align__(1024) __nv_bfloat16  g_eb [(size_t)BB * NN * NN]; // bf16 exp(s)
__device__ __align__(1024) float          g_rs [(size_t)BB * NN];      // fp32 row sums

// ---------------------------------------------------------------------------
// Helpers
// ---------------------------------------------------------------------------
__device__ __forceinline__ uint32_t smem_to_u32(const void* p) {
    uint32_t a;
    asm("{ .reg .u64 t; cvta.to.shared.u64 t, %1; cvt.u32.u64 %0, t; }"
        : "=r"(a) : "l"(p));
    return a;
}

#define MBARRIER_INIT(addr, cnt) \
    asm volatile("mbarrier.init.shared.b64 [%0], %1;" \
        :: "r"((uint32_t)(addr)), "r"((uint32_t)(cnt)) : "memory")
#define MBARRIER_EXPECT_TX(addr, bytes) \
    asm volatile("mbarrier.arrive.expect_tx.shared.b64 _, [%0], %1;" \
        :: "r"((uint32_t)(addr)), "r"((uint32_t)(bytes)) : "memory")
#define MBARRIER_ARRIVE(addr) \
    asm volatile("mbarrier.arrive.shared.b64 _, [%0];" \
        :: "r"((uint32_t)(addr)) : "memory")
#define MBARRIER_WAIT_PARITY(addr, parity) do { \
    uint32_t _m = (uint32_t)(addr); uint32_t _p = (uint32_t)(parity); uint32_t _d; \
    asm volatile("{\n\t.reg .pred p;\n\t" \
        "mbarrier.try_wait.parity.shared.b64 p, [%1], %2;\n\t" \
        "selp.b32 %0, 1, 0, p;\n\t}" : "=r"(_d) : "r"(_m), "r"(_p) : "memory"); \
    if (!_d) { \
        asm volatile("{\n\t.reg .pred P1;\n\tWL_%=:\n\t" \
            "mbarrier.try_wait.parity.shared.b64 P1, [%0], %1, 0x989680;\n\t" \
            "@P1 bra.uni WD_%=;\n\tbra.uni WL_%=;\n\tWD_%=:\n\t}" \
            :: "r"(_m), "r"(_p) : "memory"); \
    } } while (0)

#define TMA_LOAD_3D(smem_addr, tmap, cx, cy, cz, mbar) \
    asm volatile( \
        "cp.async.bulk.tensor.3d.shared::cta.global.tile.mbarrier::complete_tx::bytes " \
        "[%0], [%1, {%2, %3, %4}], [%5];" \
        :: "r"((uint32_t)(smem_addr)), "l"(tmap), \
           "r"((int32_t)(cx)), "r"((int32_t)(cy)), "r"((int32_t)(cz)), \
           "r"((uint32_t)(mbar)) : "memory")

#define LDSM_X4(r0, r1, r2, r3, addr) \
    asm volatile("ldmatrix.sync.aligned.m8n8.x4.shared.b16 {%0,%1,%2,%3}, [%4];" \
        : "=r"(r0), "=r"(r1), "=r"(r2), "=r"(r3) : "r"(addr))

__device__ __forceinline__ void mma_f16(float* d, const uint32_t* a, const uint32_t* b) {
    asm volatile(
        "mma.sync.aligned.m16n8k16.row.col.f32.f16.f16.f32 "
        "{%0,%1,%2,%3}, {%4,%5,%6,%7}, {%8,%9}, {%0,%1,%2,%3};"
        : "+f"(d[0]), "+f"(d[1]), "+f"(d[2]), "+f"(d[3])
        : "r"(a[0]), "r"(a[1]), "r"(a[2]), "r"(a[3]), "r"(b[0]), "r"(b[1]));
}
__device__ __forceinline__ void mma_bf16(float* d, const uint32_t* a, const uint32_t* b) {
    asm volatile(
        "mma.sync.aligned.m16n8k16.row.col.f32.bf16.bf16.f32 "
        "{%0,%1,%2,%3}, {%4,%5,%6,%7}, {%8,%9}, {%0,%1,%2,%3};"
        : "+f"(d[0]), "+f"(d[1]), "+f"(d[2]), "+f"(d[3])
        : "r"(a[0]), "r"(a[1]), "r"(a[2]), "r"(a[3]), "r"(b[0]), "r"(b[1]));
}

// ---------------------------------------------------------------------------
// Fused prep: xT transpose+fp16 (all CTAs) + weight prep (first 1024 CTAs)
// grid (128, 16, 2) x 256 threads
// ---------------------------------------------------------------------------
__global__ __launch_bounds__(256) void fusedprep_kernel(
    const float* __restrict__ x,
    const float* __restrict__ Wv,
    const float* __restrict__ Wq, const float* __restrict__ bq,
    const float* __restrict__ Wk, const float* __restrict__ bk)
{
    __shared__ float t[32][33];
    const int b  = blockIdx.z;
    const int n0 = blockIdx.x * 32, c0 = blockIdx.y * 32;
    const int tx = threadIdx.x & 31, ty = threadIdx.x >> 5;
    const float* xb = x + (size_t)b * CC * NN;
    #pragma unroll
    for (int i = 0; i < 32; i += 8)
        t[ty + i][tx] = xb[(size_t)(c0 + ty + i) * NN + n0 + tx];

    // weight prep on first 1024 linear CTAs (independent of the smem tile)
    const int bid = (blockIdx.z * 16 + blockIdx.y) * 128 + blockIdx.x;
    if (bid < 1024) {
        int i = bid * 256 + threadIdx.x;        // over CC*CC
        g_wrh[i] = __float2half_rn(Wv[i]);
        if (i < QK * CC) {
            int r = i >> 9, c = i & 511;
            g_wqkh[i] = __float2half_rn(r < DD ? Wq[(size_t)r * CC + c]
                                               : Wk[(size_t)(r - DD) * CC + c]);
        }
        if (i < QK) g_bqk[i] = (i < DD) ? bq[i] : bk[i - DD];
        if (i < BB * NN) g_rs[i] = 0.0f;
    }

    __syncthreads();
    __half* o = g_xTh + (size_t)b * NN * CC;
    #pragma unroll
    for (int i = 0; i < 32; i += 8)
        o[(size_t)(n0 + ty + i) * CC + c0 + tx] = __float2half_rn(t[tx][ty + i]);
}

// ---------------------------------------------------------------------------
// qk-projection kernel (17 warps): BM=64, BN=128, BK=64, fp16 out.
// ---------------------------------------------------------------------------
constexpr int BN = 128;
constexpr int NSTAGE = 3;
constexpr int B16_BY = BN * 128;

__global__ __launch_bounds__(544)
void qkproj_kernel(const __grid_constant__ CUtensorMap tma_a,
                   const __grid_constant__ CUtensorMap tma_b,
                   const float* __restrict__ bias,
                   __half* __restrict__ outp)
{
    constexpr int A_BY = 64 * 128;
    constexpr int STG  = A_BY + B16_BY;

    __shared__ __align__(8) uint64_t s_bar[2 * NSTAGE];
    extern __shared__ char dsm[];
    const uint32_t dbase = (smem_to_u32(dsm) + 1023) & ~1023u;
    const uint32_t sbar  = smem_to_u32(s_bar);

    const int tid = threadIdx.x, wid = tid >> 5, lid = tid & 31;
    const int mBase = blockIdx.y * 64;
    const int nBase = blockIdx.x * BN;
    const int b     = blockIdx.z;
    const int nchunk = CC / 64;

    if (tid == 0) {
        #pragma unroll
        for (int s = 0; s < NSTAGE; s++) {
            MBARRIER_INIT(sbar + s * 16, 1);
            MBARRIER_INIT(sbar + s * 16 + 8, 16);
        }
    }
    __syncthreads();

    if (tid == 512) {
        int ph = 1, st = 0;
        for (int c = 0; c < nchunk; c++) {
            MBARRIER_WAIT_PARITY(sbar + st * 16 + 8, ph);
            MBARRIER_EXPECT_TX(sbar + st * 16, STG);
            TMA_LOAD_3D(dbase + st * STG,        &tma_a, c * 64, mBase, b, sbar + st * 16);
            TMA_LOAD_3D(dbase + st * STG + A_BY, &tma_b, c * 64, nBase, 0, sbar + st * 16);
            if (++st == NSTAGE) { st = 0; ph ^= 1; }
        }
    }

    if (wid < 16) {
        const int wm = wid & 3, wn = wid >> 2;
        const int mWarp = wm * 16, nWarp = wn * 32;
        const int laneA = lid & 15;
        const int hAu   = (lid >> 4) & 1;
        const int laneB = (lid & 7) + ((lid & 16) ? 8 : 0);
        const int hBu   = (lid >> 3) & 1;
        const int xor7  = lid & 7;

        float cacc[4][4] = {};

        int ph = 0, st = 0;
        for (int c = 0; c < nchunk; c++) {
            MBARRIER_WAIT_PARITY(sbar + st * 16, ph);
            const uint32_t Ab = dbase + st * STG;
            const uint32_t Bb = Ab + A_BY;
            const uint32_t aRowAddr = Ab + (mWarp + laneA) * 128;
            const uint32_t bRowAddr = Bb + (nWarp + laneB) * 128;

            #pragma unroll
            for (int ks = 0; ks < 4; ks++) {
                uint32_t af[4];
                uint32_t bf[4][2];
                const uint32_t cA = (uint32_t)(((2 * ks + hAu) ^ xor7) << 4);
                const uint32_t cB = (uint32_t)(((2 * ks + hBu) ^ xor7) << 4);
                LDSM_X4(af[0], af[1], af[2], af[3], aRowAddr + cA);
                #pragma unroll
                for (int p = 0; p < 2; p++) {
                    uint32_t r0, r1, r2, r3;
                    LDSM_X4(r0, r1, r2, r3, bRowAddr + p * (16 * 128) + cB);
                    bf[2*p][0] = r0; bf[2*p][1] = r1;
                    bf[2*p+1][0] = r2; bf[2*p+1][1] = r3;
                }
                #pragma unroll
                for (int nt = 0; nt < 4; nt++)
                    mma_f16(cacc[nt], af, bf[nt]);
            }
            if (lid == 0) MBARRIER_ARRIVE(sbar + st * 16 + 8);
            if (++st == NSTAGE) { st = 0; ph ^= 1; }
        }

        const int g = lid >> 2, t4 = lid & 3;
        const int r0 = mBase + mWarp + g;
        const int r1 = r0 + 8;
        __half* ob = outp + (size_t)b * NN * QK;
        #pragma unroll
        for (int nt = 0; nt < 4; nt++) {
            const int col = nBase + nWarp + nt * 8 + t4 * 2;
            const float bc0 = bias[col], bc1 = bias[col + 1];
            *(__half2*)&ob[(size_t)r0 * QK + col] =
                __floats2half2_rn(cacc[nt][0] + bc0, cacc[nt][1] + bc1);
            *(__half2*)&ob[(size_t)r1 * QK + col] =
                __floats2half2_rn(cacc[nt][2] + bc0, cacc[nt][3] + bc1);
        }
    }
}

// ---------------------------------------------------------------------------
// 8-warp compute + 1 producer GEMM: tile 128x128x64, 2 CTAs/SM.
// mode 0: bf16 out = C + bias[row]      (v-proj, fp16 mma)
// mode 1: fp32 out = gamma*C/rs[col]+x  (AV, bf16 mma)
// mode 2: bf16 out = exp(C); rs atomics (scores, fp16 mma)
// ---------------------------------------------------------------------------
constexpr int G8_A_BY = 128 * 128;                // 16 KB
constexpr int G8_STG  = G8_A_BY + B16_BY;         // 32 KB
constexpr int G8_DSMEM = NSTAGE * G8_STG + 1024;  // 99328 -> 2 CTAs/SM

template<int USE_BF16>
__global__ __launch_bounds__(288)
void gemm8w_kernel(const __grid_constant__ CUtensorMap tma_a,
                   const __grid_constant__ CUtensorMap tma_b,
                   int k_total, int mode, int a_batched, int b_batched,
                   int a_koff, int b_koff, int swap_xy,
                   const float* __restrict__ aux,     // mode0: bias, mode1: x
                   float* __restrict__ rs,
                   const float* __restrict__ gamma,
                   void* __restrict__ outp, size_t out_bstride, int out_rstride)
{
    __shared__ __align__(8) uint64_t s_bar[2 * NSTAGE];
    extern __shared__ char dsm[];
    const uint32_t dbase = (smem_to_u32(dsm) + 1023) & ~1023u;
    const uint32_t sbar  = smem_to_u32(s_bar);

    const int tid = threadIdx.x, wid = tid >> 5, lid = tid & 31;
    const int mBase = (swap_xy ? blockIdx.x : blockIdx.y) * 128;
    const int nBase = (swap_xy ? blockIdx.y : blockIdx.x) * 128;
    const int b     = blockIdx.z;
    const int nchunk = k_total / 64;

    if (tid == 0) {
        #pragma unroll
        for (int s = 0; s < NSTAGE; s++) {
            MBARRIER_INIT(sbar + s * 16, 1);
            MBARRIER_INIT(sbar + s * 16 + 8, 8);
        }
    }
    __syncthreads();

    if (tid == 256) {
        const int az = a_batched ? b : 0;
        const int bz = b_batched ? b : 0;
        int ph = 1, st = 0;
        for (int c = 0; c < nchunk; c++) {
            MBARRIER_WAIT_PARITY(sbar + st * 16 + 8, ph);
            MBARRIER_EXPECT_TX(sbar + st * 16, G8_STG);
            TMA_LOAD_3D(dbase + st * G8_STG,           &tma_a, a_koff + c * 64, mBase, az, sbar + st * 16);
            TMA_LOAD_3D(dbase + st * G8_STG + G8_A_BY, &tma_b, b_koff + c * 64, nBase, bz, sbar + st * 16);
            if (++st == NSTAGE) { st = 0; ph ^= 1; }
        }
    }

    if (wid < 8) {
        const int wm = wid & 1, wn = wid >> 1;          // 2 x 4 warp grid
        const int mWarp = wm * 64, nWarp = wn * 32;
        const int laneA = lid & 15;
        const int hAu   = (lid >> 4) & 1;
        const int laneB = (lid & 7) + ((lid & 16) ? 8 : 0);
        const int hBu   = (lid >> 3) & 1;
        const int xor7  = lid & 7;

        float cacc[4][4][4] = {};

        int ph = 0, st = 0;
        for (int c = 0; c < nchunk; c++) {
            MBARRIER_WAIT_PARITY(sbar + st * 16, ph);
            const uint32_t Ab = dbase + st * G8_STG;
            const uint32_t Bb = Ab + G8_A_BY;
            const uint32_t aRowAddr = Ab + (mWarp + laneA) * 128;
            const uint32_t bRowAddr = Bb + (nWarp + laneB) * 128;

            #pragma unroll
            for (int ks = 0; ks < 4; ks++) {
                uint32_t af[4][4];
                uint32_t bf[4][2];
                const uint32_t cA = (uint32_t)(((2 * ks + hAu) ^ xor7) << 4);
                const uint32_t cB = (uint32_t)(((2 * ks + hBu) ^ xor7) << 4);
                #pragma unroll
                for (int mt = 0; mt < 4; mt++)
                    LDSM_X4(af[mt][0], af[mt][1], af[mt][2], af[mt][3],
                            aRowAddr + mt * (16 * 128) + cA);
                #pragma unroll
                for (int p = 0; p < 2; p++) {
                    uint32_t r0, r1, r2, r3;
                    LDSM_X4(r0, r1, r2, r3, bRowAddr + p * (16 * 128) + cB);
                    bf[2*p][0] = r0; bf[2*p][1] = r1;
                    bf[2*p+1][0] = r2; bf[2*p+1][1] = r3;
                }
                #pragma unroll
                for (int mt = 0; mt < 4; mt++)
                    #pragma unroll
                    for (int nt = 0; nt < 4; nt++) {
                        if (USE_BF16) mma_bf16(cacc[mt][nt], af[mt], bf[nt]);
                        else          mma_f16 (cacc[mt][nt], af[mt], bf[nt]);
                    }
            }
            if (lid == 0) MBARRIER_ARRIVE(sbar + st * 16 + 8);
            if (++st == NSTAGE) { st = 0; ph ^= 1; }
        }

        // ---- epilogue ----
        const int g = lid >> 2, t4 = lid & 3;
        float* rs_b = rs + (size_t)b * NN;

        if (mode == 1) {
            const float gm = gamma[0];
            const float* xb = aux + (size_t)b * out_bstride;
            float* ob = (float*)outp + (size_t)b * out_bstride;
            #pragma unroll
            for (int mt = 0; mt < 4; mt++) {
                const int r0 = mBase + mWarp + mt * 16 + g;
                const int r1 = r0 + 8;
                #pragma unroll
                for (int nt = 0; nt < 4; nt++) {
                    const int col = nBase + nWarp + nt * 8 + t4 * 2;
                    const float i0 = __fdividef(1.0f, rs_b[col]);
                    const float i1 = __fdividef(1.0f, rs_b[col + 1]);
                    const float2 x0 = *(const float2*)&xb[(size_t)r0 * out_rstride + col];
                    const float2 x1 = *(const float2*)&xb[(size_t)r1 * out_rstride + col];
                    *(float2*)&ob[(size_t)r0 * out_rstride + col] =
                        make_float2(gm * cacc[mt][nt][0] * i0 + x0.x,
                                    gm * cacc[mt][nt][1] * i1 + x0.y);
                    *(float2*)&ob[(size_t)r1 * out_rstride + col] =
                        make_float2(gm * cacc[mt][nt][2] * i0 + x1.x,
                                    gm * cacc[mt][nt][3] * i1 + x1.y);
                }
            }
        } else {
            __nv_bfloat16* ob = (__nv_bfloat16*)outp + (size_t)b * out_bstride;
            #pragma unroll
            for (int mt = 0; mt < 4; mt++) {
                const int r0 = mBase + mWarp + mt * 16 + g;
                const int r1 = r0 + 8;
                float bias0 = 0.f, bias1 = 0.f;
                if (mode == 0) { bias0 = aux[r0]; bias1 = aux[r1]; }
                float s0 = 0.f, s1 = 0.f;
                #pragma unroll
                for (int nt = 0; nt < 4; nt++) {
                    const int col = nBase + nWarp + nt * 8 + t4 * 2;
                    float v00 = cacc[mt][nt][0], v01 = cacc[mt][nt][1];
                    float v10 = cacc[mt][nt][2], v11 = cacc[mt][nt][3];
                    if (mode == 0) {
                        v00 += bias0; v01 += bias0; v10 += bias1; v11 += bias1;
                    } else {    // mode 2
                        v00 = __expf(v00); v01 = __expf(v01);
                        v10 = __expf(v10); v11 = __expf(v11);
                        s0 += v00 + v01; s1 += v10 + v11;
                    }
                    *(__nv_bfloat162*)&ob[(size_t)r0 * out_rstride + col] =
                        __floats2bfloat162_rn(v00, v01);
                    *(__nv_bfloat162*)&ob[(size_t)r1 * out_rstride + col] =
                        __floats2bfloat162_rn(v10, v11);
                }
                if (mode == 2) {
                    s0 += __shfl_xor_sync(0xFFFFFFFFu, s0, 1);
                    s0 += __shfl_xor_sync(0xFFFFFFFFu, s0, 2);
                    s1 += __shfl_xor_sync(0xFFFFFFFFu, s1, 1);
                    s1 += __shfl_xor_sync(0xFFFFFFFFu, s1, 2);
                    if (t4 == 0) {
                        atomicAdd(&rs_b[r0], s0);
                        atomicAdd(&rs_b[r1], s1);
                    }
                }
            }
        }
    }
}

// ---------------------------------------------------------------------------
// Host side
// ---------------------------------------------------------------------------
typedef CUresult (*EncodeFn)(CUtensorMap*, CUtensorMapDataType, cuuint32_t, void*,
                             const cuuint64_t*, const cuuint64_t*, const cuuint32_t*,
                             const cuuint32_t*, CUtensorMapInterleave, CUtensorMapSwizzle,
                             CUtensorMapL2promotion, CUtensorMapFloatOOBfill);

static void build_tm(EncodeFn enc, CUtensorMap* tm, void* ptr,
                     uint64_t d0, uint64_t d1, uint64_t d2,
                     uint64_t s1b, uint64_t s2b, uint32_t b0, uint32_t b1)
{
    cuuint64_t dims[3] = {d0, d1, d2};
    cuuint64_t str[2]  = {s1b, s2b};
    cuuint32_t box[3]  = {b0, b1, 1};
    cuuint32_t es[3]   = {1, 1, 1};
    enc(tm, CU_TENSOR_MAP_DATA_TYPE_UINT16, 3, ptr, dims, str, box, es,
        CU_TENSOR_MAP_INTERLEAVE_NONE, CU_TENSOR_MAP_SWIZZLE_128B,
        CU_TENSOR_MAP_L2_PROMOTION_L2_128B, CU_TENSOR_MAP_FLOAT_OOB_FILL_NONE);
}

extern "C" void kernel_launch(void* const* d_in, const int* in_sizes, int n_in,
                              void* d_out, int out_size)
{
    (void)in_sizes; (void)n_in; (void)out_size;
    const float* x     = (const float*)d_in[0];
    const float* Wq    = (const float*)d_in[1];
    const float* bq    = (const float*)d_in[2];
    const float* Wk    = (const float*)d_in[3];
    const float* bk    = (const float*)d_in[4];
    const float* Wv    = (const float*)d_in[5];
    const float* bv    = (const float*)d_in[6];
    const float* gamma = (const float*)d_in[7];
    float* out = (float*)d_out;

    EncodeFn enc = nullptr;
    cudaDriverEntryPointQueryResult qr;
    cudaGetDriverEntryPointByVersion("cuTensorMapEncodeTiled", (void**)&enc, 12000,
                                     cudaEnableDefault, &qr);

    void *pqk, *pvb, *peb, *pxT, *pwr, *pwqk, *pbqk, *prs;
    cudaGetSymbolAddress(&pqk,  g_qkh);
    cudaGetSymbolAddress(&pvb,  g_vb);
    cudaGetSymbolAddress(&peb,  g_eb);
    cudaGetSymbolAddress(&pxT,  g_xTh);
    cudaGetSymbolAddress(&pwr,  g_wrh);
    cudaGetSymbolAddress(&pwqk, g_wqkh);
    cudaGetSymbolAddress(&pbqk, g_bqk);
    cudaGetSymbolAddress(&prs,  g_rs);

    CUtensorMap tmXT_A64, tmXT_B, tmWQK, tmWV, tmQKa, tmQKb, tmVb, tmEb;
    build_tm(enc, &tmXT_A64, pxT, CC, NN, BB, (uint64_t)CC * 2, (uint64_t)NN * CC * 2, 64, 64);
    build_tm(enc, &tmXT_B,   pxT, CC, NN, BB, (uint64_t)CC * 2, (uint64_t)NN * CC * 2, 64, 128);
    build_tm(enc, &tmWQK, pwqk, CC, QK, 1, (uint64_t)CC * 2, (uint64_t)QK * CC * 2, 64, 128);
    build_tm(enc, &tmWV,  pwr,  CC, CC, 1, (uint64_t)CC * 2, (uint64_t)CC * CC * 2, 64, 128);
    build_tm(enc, &tmQKa, pqk, QK, NN, BB, (uint64_t)QK * 2, (uint64_t)NN * QK * 2, 64, 128);
    build_tm(enc, &tmQKb, pqk, QK, NN, BB, (uint64_t)QK * 2, (uint64_t)NN * QK * 2, 64, 128);
    build_tm(enc, &tmVb, pvb, NN, CC, BB, (uint64_t)NN * 2, (uint64_t)CC * NN * 2, 64, 128);
    build_tm(enc, &tmEb, peb, NN, NN, BB, (uint64_t)NN * 2, (uint64_t)NN * NN * 2, 64, 128);

    constexpr int DS1 = NSTAGE * (64 * 128 + B16_BY) + 1024;
    cudaFuncSetAttribute(qkproj_kernel, cudaFuncAttributeMaxDynamicSharedMemorySize, DS1);
    cudaFuncSetAttribute(gemm8w_kernel<0>, cudaFuncAttributeMaxDynamicSharedMemorySize, G8_DSMEM);
    cudaFuncSetAttribute(gemm8w_kernel<1>, cudaFuncAttributeMaxDynamicSharedMemorySize, G8_DSMEM);

    float* frs = (float*)prs;

    // 1. fused prep: xT transpose/convert + weight conversion + rs zero
    fusedprep_kernel<<<dim3(NN / 32, CC / 32, BB), 256>>>(x, Wv, Wq, bq, Wk, bk);
    // 2. qk projection: 128 CTAs, K=512, fp16 out
    qkproj_kernel<<<dim3(1, NN / 64, BB), 544, DS1>>>(
        tmXT_A64, tmWQK, (const float*)pbqk, (__half*)pqk);
    // 3. v projection (8w, 2 CTAs/SM): g_vb[c][n] = bf16(Wv·xT^T + bv), K=512
    gemm8w_kernel<0><<<dim3(NN / 128, CC / 128, BB), 288, G8_DSMEM>>>(
        tmWV, tmXT_B, CC, 0, 0, 1, 0, 0, 0, bv, frs, gamma,
        pvb, (size_t)CC * NN, NN);
    // 4. scores (8w): g_eb[i][j] = bf16(exp(q·k)), fp32 rowsums, K=64
    gemm8w_kernel<0><<<dim3(NN / 128, NN / 128, BB), 288, G8_DSMEM>>>(
        tmQKa, tmQKb, DD, 2, 1, 1, 0, DD, 0, nullptr, frs, gamma,
        peb, (size_t)NN * NN, NN);
    // 5. AV (8w, bf16 mma): out = gamma*(v·e^T)/rs + x, K=4096
    //    c-tiles fastest -> e tile shared in L2
    gemm8w_kernel<1><<<dim3(CC / 128, NN / 128, BB), 288, G8_DSMEM>>>(
        tmVb, tmEb, NN, 1, 1, 1, 0, 0, 1, x, frs, gamma,
        out, (size_t)CC * NN, NN);
}

// round 17
// speedup vs baseline: 1.0550x; 1.0020x over previous
#include <cuda_runtime.h>
#include <cuda.h>
#include <cuda_fp16.h>
#include <cuda_bf16.h>
#include <cstdint>
#include <math.h>

constexpr int BB = 2;
constexpr int CC = 512;
constexpr int NN = 4096;
constexpr int DD = 64;
constexpr int QK = 128;

// ---------------------------------------------------------------------------
// Scratch
// ---------------------------------------------------------------------------
__device__ __align__(1024) __half         g_qkh[(size_t)BB * NN * QK]; // fp16 q|k
__device__ __align__(1024) __nv_bfloat16  g_vb [(size_t)BB * CC * NN]; // bf16 v
__device__ __align__(1024) __half         g_xTh[(size_t)BB * NN * CC]; // fp16 xT
__device__ __align__(1024) __half         g_wrh[(size_t)CC * CC];      // fp16 Wv
__device__ __align__(1024) __half         g_wqkh[(size_t)QK * CC];     // fp16 Wq|Wk
__device__ __align__(1024) float          g_bqk[QK];
__device__ __align__(1024) __nv_bfloat16  g_eb [(size_t)BB * NN * NN]; // bf16 exp(s)
__device__ __align__(1024) float          g_rs [(size_t)BB * NN];      // fp32 row sums

// ---------------------------------------------------------------------------
// Helpers
// ---------------------------------------------------------------------------
__device__ __forceinline__ uint32_t smem_to_u32(const void* p) {
    uint32_t a;
    asm("{ .reg .u64 t; cvta.to.shared.u64 t, %1; cvt.u32.u64 %0, t; }"
        : "=r"(a) : "l"(p));
    return a;
}

#define MBARRIER_INIT(addr, cnt) \
    asm volatile("mbarrier.init.shared.b64 [%0], %1;" \
        :: "r"((uint32_t)(addr)), "r"((uint32_t)(cnt)) : "memory")
#define MBARRIER_EXPECT_TX(addr, bytes) \
    asm volatile("mbarrier.arrive.expect_tx.shared.b64 _, [%0], %1;" \
        :: "r"((uint32_t)(addr)), "r"((uint32_t)(bytes)) : "memory")
#define MBARRIER_ARRIVE(addr) \
    asm volatile("mbarrier.arrive.shared.b64 _, [%0];" \
        :: "r"((uint32_t)(addr)) : "memory")
#define MBARRIER_WAIT_PARITY(addr, parity) do { \
    uint32_t _m = (uint32_t)(addr); uint32_t _p = (uint32_t)(parity); uint32_t _d; \
    asm volatile("{\n\t.reg .pred p;\n\t" \
        "mbarrier.try_wait.parity.shared.b64 p, [%1], %2;\n\t" \
        "selp.b32 %0, 1, 0, p;\n\t}" : "=r"(_d) : "r"(_m), "r"(_p) : "memory"); \
    if (!_d) { \
        asm volatile("{\n\t.reg .pred P1;\n\tWL_%=:\n\t" \
            "mbarrier.try_wait.parity.shared.b64 P1, [%0], %1, 0x989680;\n\t" \
            "@P1 bra.uni WD_%=;\n\tbra.uni WL_%=;\n\tWD_%=:\n\t}" \
            :: "r"(_m), "r"(_p) : "memory"); \
    } } while (0)

#define TMA_LOAD_3D(smem_addr, tmap, cx, cy, cz, mbar) \
    asm volatile( \
        "cp.async.bulk.tensor.3d.shared::cta.global.tile.mbarrier::complete_tx::bytes " \
        "[%0], [%1, {%2, %3, %4}], [%5];" \
        :: "r"((uint32_t)(smem_addr)), "l"(tmap), \
           "r"((int32_t)(cx)), "r"((int32_t)(cy)), "r"((int32_t)(cz)), \
           "r"((uint32_t)(mbar)) : "memory")

#define LDSM_X4(r0, r1, r2, r3, addr) \
    asm volatile("ldmatrix.sync.aligned.m8n8.x4.shared.b16 {%0,%1,%2,%3}, [%4];" \
        : "=r"(r0), "=r"(r1), "=r"(r2), "=r"(r3) : "r"(addr))

__device__ __forceinline__ void mma_f16(float* d, const uint32_t* a, const uint32_t* b) {
    asm volatile(
        "mma.sync.aligned.m16n8k16.row.col.f32.f16.f16.f32 "
        "{%0,%1,%2,%3}, {%4,%5,%6,%7}, {%8,%9}, {%0,%1,%2,%3};"
        : "+f"(d[0]), "+f"(d[1]), "+f"(d[2]), "+f"(d[3])
        : "r"(a[0]), "r"(a[1]), "r"(a[2]), "r"(a[3]), "r"(b[0]), "r"(b[1]));
}
__device__ __forceinline__ void mma_bf16(float* d, const uint32_t* a, const uint32_t* b) {
    asm volatile(
        "mma.sync.aligned.m16n8k16.row.col.f32.bf16.bf16.f32 "
        "{%0,%1,%2,%3}, {%4,%5,%6,%7}, {%8,%9}, {%0,%1,%2,%3};"
        : "+f"(d[0]), "+f"(d[1]), "+f"(d[2]), "+f"(d[3])
        : "r"(a[0]), "r"(a[1]), "r"(a[2]), "r"(a[3]), "r"(b[0]), "r"(b[1]));
}

// ---------------------------------------------------------------------------
// Fused prep: xT transpose+fp16 (all CTAs) + weight prep (first 1024 CTAs)
// grid (128, 16, 2) x 256 threads
// ---------------------------------------------------------------------------
__global__ __launch_bounds__(256) void fusedprep_kernel(
    const float* __restrict__ x,
    const float* __restrict__ Wv,
    const float* __restrict__ Wq, const float* __restrict__ bq,
    const float* __restrict__ Wk, const float* __restrict__ bk)
{
    __shared__ float t[32][33];
    const int b  = blockIdx.z;
    const int n0 = blockIdx.x * 32, c0 = blockIdx.y * 32;
    const int tx = threadIdx.x & 31, ty = threadIdx.x >> 5;
    const float* xb = x + (size_t)b * CC * NN;
    #pragma unroll
    for (int i = 0; i < 32; i += 8)
        t[ty + i][tx] = xb[(size_t)(c0 + ty + i) * NN + n0 + tx];

    // weight prep on first 1024 linear CTAs (independent of the smem tile)
    const int bid = (blockIdx.z * 16 + blockIdx.y) * 128 + blockIdx.x;
    if (bid < 1024) {
        int i = bid * 256 + threadIdx.x;        // over CC*CC
        g_wrh[i] = __float2half_rn(Wv[i]);
        if (i < QK * CC) {
            int r = i >> 9, c = i & 511;
            g_wqkh[i] = __float2half_rn(r < DD ? Wq[(size_t)r * CC + c]
                                               : Wk[(size_t)(r - DD) * CC + c]);
        }
        if (i < QK) g_bqk[i] = (i < DD) ? bq[i] : bk[i - DD];
        if (i < BB * NN) g_rs[i] = 0.0f;
    }

    __syncthreads();
    __half* o = g_xTh + (size_t)b * NN * CC;
    #pragma unroll
    for (int i = 0; i < 32; i += 8)
        o[(size_t)(n0 + ty + i) * CC + c0 + tx] = __float2half_rn(t[tx][ty + i]);
}

// ---------------------------------------------------------------------------
// qk-projection kernel (17 warps): BM=64, BN=128, BK=64, fp16 out.
// ---------------------------------------------------------------------------
constexpr int BN = 128;
constexpr int NSTAGE = 3;
constexpr int B16_BY = BN * 128;

__global__ __launch_bounds__(544)
void qkproj_kernel(const __grid_constant__ CUtensorMap tma_a,
                   const __grid_constant__ CUtensorMap tma_b,
                   const float* __restrict__ bias,
                   __half* __restrict__ outp)
{
    constexpr int A_BY = 64 * 128;
    constexpr int STG  = A_BY + B16_BY;

    __shared__ __align__(8) uint64_t s_bar[2 * NSTAGE];
    extern __shared__ char dsm[];
    const uint32_t dbase = (smem_to_u32(dsm) + 1023) & ~1023u;
    const uint32_t sbar  = smem_to_u32(s_bar);

    const int tid = threadIdx.x, wid = tid >> 5, lid = tid & 31;
    const int mBase = blockIdx.y * 64;
    const int nBase = blockIdx.x * BN;
    const int b     = blockIdx.z;
    const int nchunk = CC / 64;

    if (tid == 0) {
        #pragma unroll
        for (int s = 0; s < NSTAGE; s++) {
            MBARRIER_INIT(sbar + s * 16, 1);
            MBARRIER_INIT(sbar + s * 16 + 8, 16);
        }
    }
    __syncthreads();

    if (tid == 512) {
        int ph = 1, st = 0;
        for (int c = 0; c < nchunk; c++) {
            MBARRIER_WAIT_PARITY(sbar + st * 16 + 8, ph);
            MBARRIER_EXPECT_TX(sbar + st * 16, STG);
            TMA_LOAD_3D(dbase + st * STG,        &tma_a, c * 64, mBase, b, sbar + st * 16);
            TMA_LOAD_3D(dbase + st * STG + A_BY, &tma_b, c * 64, nBase, 0, sbar + st * 16);
            if (++st == NSTAGE) { st = 0; ph ^= 1; }
        }
    }

    if (wid < 16) {
        const int wm = wid & 3, wn = wid >> 2;
        const int mWarp = wm * 16, nWarp = wn * 32;
        const int laneA = lid & 15;
        const int hAu   = (lid >> 4) & 1;
        const int laneB = (lid & 7) + ((lid & 16) ? 8 : 0);
        const int hBu   = (lid >> 3) & 1;
        const int xor7  = lid & 7;

        float cacc[4][4] = {};

        int ph = 0, st = 0;
        for (int c = 0; c < nchunk; c++) {
            MBARRIER_WAIT_PARITY(sbar + st * 16, ph);
            const uint32_t Ab = dbase + st * STG;
            const uint32_t Bb = Ab + A_BY;
            const uint32_t aRowAddr = Ab + (mWarp + laneA) * 128;
            const uint32_t bRowAddr = Bb + (nWarp + laneB) * 128;

            #pragma unroll
            for (int ks = 0; ks < 4; ks++) {
                uint32_t af[4];
                uint32_t bf[4][2];
                const uint32_t cA = (uint32_t)(((2 * ks + hAu) ^ xor7) << 4);
                const uint32_t cB = (uint32_t)(((2 * ks + hBu) ^ xor7) << 4);
                LDSM_X4(af[0], af[1], af[2], af[3], aRowAddr + cA);
                #pragma unroll
                for (int p = 0; p < 2; p++) {
                    uint32_t r0, r1, r2, r3;
                    LDSM_X4(r0, r1, r2, r3, bRowAddr + p * (16 * 128) + cB);
                    bf[2*p][0] = r0; bf[2*p][1] = r1;
                    bf[2*p+1][0] = r2; bf[2*p+1][1] = r3;
                }
                #pragma unroll
                for (int nt = 0; nt < 4; nt++)
                    mma_f16(cacc[nt], af, bf[nt]);
            }
            if (lid == 0) MBARRIER_ARRIVE(sbar + st * 16 + 8);
            if (++st == NSTAGE) { st = 0; ph ^= 1; }
        }

        const int g = lid >> 2, t4 = lid & 3;
        const int r0 = mBase + mWarp + g;
        const int r1 = r0 + 8;
        __half* ob = outp + (size_t)b * NN * QK;
        #pragma unroll
        for (int nt = 0; nt < 4; nt++) {
            const int col = nBase + nWarp + nt * 8 + t4 * 2;
            const float bc0 = bias[col], bc1 = bias[col + 1];
            *(__half2*)&ob[(size_t)r0 * QK + col] =
                __floats2half2_rn(cacc[nt][0] + bc0, cacc[nt][1] + bc1);
            *(__half2*)&ob[(size_t)r1 * QK + col] =
                __floats2half2_rn(cacc[nt][2] + bc0, cacc[nt][3] + bc1);
        }
    }
}

// ---------------------------------------------------------------------------
// 8-warp compute + 1 producer GEMM: tile 128x128x64, 2 CTAs/SM.
// mode 0: bf16 out = C + bias[row]      (v-proj, fp16 mma)
// mode 1: fp32 out = gamma*C/rs[col]+x  (AV, bf16 mma)
// mode 2: bf16 out = exp(C); rs atomics (scores, fp16 mma)
// ---------------------------------------------------------------------------
constexpr int G8_A_BY = 128 * 128;                // 16 KB
constexpr int G8_STG  = G8_A_BY + B16_BY;         // 32 KB
constexpr int G8_DSMEM = NSTAGE * G8_STG + 1024;  // 99328 -> 2 CTAs/SM

template<int USE_BF16>
__global__ __launch_bounds__(288)
void gemm8w_kernel(const __grid_constant__ CUtensorMap tma_a,
                   const __grid_constant__ CUtensorMap tma_b,
                   int k_total, int mode, int a_batched, int b_batched,
                   int a_koff, int b_koff, int swap_xy,
                   const float* __restrict__ aux,     // mode0: bias, mode1: x
                   float* __restrict__ rs,
                   const float* __restrict__ gamma,
                   void* __restrict__ outp, size_t out_bstride, int out_rstride)
{
    __shared__ __align__(8) uint64_t s_bar[2 * NSTAGE];
    extern __shared__ char dsm[];
    const uint32_t dbase = (smem_to_u32(dsm) + 1023) & ~1023u;
    const uint32_t sbar  = smem_to_u32(s_bar);

    const int tid = threadIdx.x, wid = tid >> 5, lid = tid & 31;
    const int mBase = (swap_xy ? blockIdx.x : blockIdx.y) * 128;
    const int nBase = (swap_xy ? blockIdx.y : blockIdx.x) * 128;
    const int b     = blockIdx.z;
    const int nchunk = k_total / 64;

    if (tid == 0) {
        #pragma unroll
        for (int s = 0; s < NSTAGE; s++) {
            MBARRIER_INIT(sbar + s * 16, 1);
            MBARRIER_INIT(sbar + s * 16 + 8, 8);
        }
    }
    __syncthreads();

    if (tid == 256) {
        const int az = a_batched ? b : 0;
        const int bz = b_batched ? b : 0;
        int ph = 1, st = 0;
        for (int c = 0; c < nchunk; c++) {
            MBARRIER_WAIT_PARITY(sbar + st * 16 + 8, ph);
            MBARRIER_EXPECT_TX(sbar + st * 16, G8_STG);
            TMA_LOAD_3D(dbase + st * G8_STG,           &tma_a, a_koff + c * 64, mBase, az, sbar + st * 16);
            TMA_LOAD_3D(dbase + st * G8_STG + G8_A_BY, &tma_b, b_koff + c * 64, nBase, bz, sbar + st * 16);
            if (++st == NSTAGE) { st = 0; ph ^= 1; }
        }
    }

    if (wid < 8) {
        const int wm = wid & 1, wn = wid >> 1;          // 2 x 4 warp grid
        const int mWarp = wm * 64, nWarp = wn * 32;
        const int laneA = lid & 15;
        const int hAu   = (lid >> 4) & 1;
        const int laneB = (lid & 7) + ((lid & 16) ? 8 : 0);
        const int hBu   = (lid >> 3) & 1;
        const int xor7  = lid & 7;

        float cacc[4][4][4] = {};

        int ph = 0, st = 0;
        for (int c = 0; c < nchunk; c++) {
            MBARRIER_WAIT_PARITY(sbar + st * 16, ph);
            const uint32_t Ab = dbase + st * G8_STG;
            const uint32_t Bb = Ab + G8_A_BY;
            const uint32_t aRowAddr = Ab + (mWarp + laneA) * 128;
            const uint32_t bRowAddr = Bb + (nWarp + laneB) * 128;

            #pragma unroll
            for (int ks = 0; ks < 4; ks++) {
                uint32_t af[4][4];
                uint32_t bf[4][2];
                const uint32_t cA = (uint32_t)(((2 * ks + hAu) ^ xor7) << 4);
                const uint32_t cB = (uint32_t)(((2 * ks + hBu) ^ xor7) << 4);
                #pragma unroll
                for (int mt = 0; mt < 4; mt++)
                    LDSM_X4(af[mt][0], af[mt][1], af[mt][2], af[mt][3],
                            aRowAddr + mt * (16 * 128) + cA);
                #pragma unroll
                for (int p = 0; p < 2; p++) {
                    uint32_t r0, r1, r2, r3;
                    LDSM_X4(r0, r1, r2, r3, bRowAddr + p * (16 * 128) + cB);
                    bf[2*p][0] = r0; bf[2*p][1] = r1;
                    bf[2*p+1][0] = r2; bf[2*p+1][1] = r3;
                }
                #pragma unroll
                for (int mt = 0; mt < 4; mt++)
                    #pragma unroll
                    for (int nt = 0; nt < 4; nt++) {
                        if (USE_BF16) mma_bf16(cacc[mt][nt], af[mt], bf[nt]);
                        else          mma_f16 (cacc[mt][nt], af[mt], bf[nt]);
                    }
            }
            if (lid == 0) MBARRIER_ARRIVE(sbar + st * 16 + 8);
            if (++st == NSTAGE) { st = 0; ph ^= 1; }
        }

        // ---- epilogue ----
        const int g = lid >> 2, t4 = lid & 3;
        float* rs_b = rs + (size_t)b * NN;

        if (mode == 1) {
            const float gm = gamma[0];
            const float* xb = aux + (size_t)b * out_bstride;
            float* ob = (float*)outp + (size_t)b * out_bstride;
            #pragma unroll
            for (int mt = 0; mt < 4; mt++) {
                const int r0 = mBase + mWarp + mt * 16 + g;
                const int r1 = r0 + 8;
                #pragma unroll
                for (int nt = 0; nt < 4; nt++) {
                    const int col = nBase + nWarp + nt * 8 + t4 * 2;
                    const float i0 = __fdividef(1.0f, rs_b[col]);
                    const float i1 = __fdividef(1.0f, rs_b[col + 1]);
                    const float2 x0 = *(const float2*)&xb[(size_t)r0 * out_rstride + col];
                    const float2 x1 = *(const float2*)&xb[(size_t)r1 * out_rstride + col];
                    *(float2*)&ob[(size_t)r0 * out_rstride + col] =
                        make_float2(gm * cacc[mt][nt][0] * i0 + x0.x,
                                    gm * cacc[mt][nt][1] * i1 + x0.y);
                    *(float2*)&ob[(size_t)r1 * out_rstride + col] =
                        make_float2(gm * cacc[mt][nt][2] * i0 + x1.x,
                                    gm * cacc[mt][nt][3] * i1 + x1.y);
                }
            }
        } else {
            __nv_bfloat16* ob = (__nv_bfloat16*)outp + (size_t)b * out_bstride;
            #pragma unroll
            for (int mt = 0; mt < 4; mt++) {
                const int r0 = mBase + mWarp + mt * 16 + g;
                const int r1 = r0 + 8;
                float bias0 = 0.f, bias1 = 0.f;
                if (mode == 0) { bias0 = aux[r0]; bias1 = aux[r1]; }
                float s0 = 0.f, s1 = 0.f;
                #pragma unroll
                for (int nt = 0; nt < 4; nt++) {
                    const int col = nBase + nWarp + nt * 8 + t4 * 2;
                    float v00 = cacc[mt][nt][0], v01 = cacc[mt][nt][1];
                    float v10 = cacc[mt][nt][2], v11 = cacc[mt][nt][3];
                    if (mode == 0) {
                        v00 += bias0; v01 += bias0; v10 += bias1; v11 += bias1;
                    } else {    // mode 2
                        v00 = __expf(v00); v01 = __expf(v01);
                        v10 = __expf(v10); v11 = __expf(v11);
                        s0 += v00 + v01; s1 += v10 + v11;
                    }
                    *(__nv_bfloat162*)&ob[(size_t)r0 * out_rstride + col] =
                        __floats2bfloat162_rn(v00, v01);
                    *(__nv_bfloat162*)&ob[(size_t)r1 * out_rstride + col] =
                        __floats2bfloat162_rn(v10, v11);
                }
                if (mode == 2) {
                    s0 += __shfl_xor_sync(0xFFFFFFFFu, s0, 1);
                    s0 += __shfl_xor_sync(0xFFFFFFFFu, s0, 2);
                    s1 += __shfl_xor_sync(0xFFFFFFFFu, s1, 1);
                    s1 += __shfl_xor_sync(0xFFFFFFFFu, s1, 2);
                    if (t4 == 0) {
                        atomicAdd(&rs_b[r0], s0);
                        atomicAdd(&rs_b[r1], s1);
                    }
                }
            }
        }
    }
}

// ---------------------------------------------------------------------------
// Host side
// ---------------------------------------------------------------------------
typedef CUresult (*EncodeFn)(CUtensorMap*, CUtensorMapDataType, cuuint32_t, void*,
                             const cuuint64_t*, const cuuint64_t*, const cuuint32_t*,
                             const cuuint32_t*, CUtensorMapInterleave, CUtensorMapSwizzle,
                             CUtensorMapL2promotion, CUtensorMapFloatOOBfill);

static void build_tm(EncodeFn enc, CUtensorMap* tm, void* ptr,
                     uint64_t d0, uint64_t d1, uint64_t d2,
                     uint64_t s1b, uint64_t s2b, uint32_t b0, uint32_t b1)
{
    cuuint64_t dims[3] = {d0, d1, d2};
    cuuint64_t str[2]  = {s1b, s2b};
    cuuint32_t box[3]  = {b0, b1, 1};
    cuuint32_t es[3]   = {1, 1, 1};
    enc(tm, CU_TENSOR_MAP_DATA_TYPE_UINT16, 3, ptr, dims, str, box, es,
        CU_TENSOR_MAP_INTERLEAVE_NONE, CU_TENSOR_MAP_SWIZZLE_128B,
        CU_TENSOR_MAP_L2_PROMOTION_L2_128B, CU_TENSOR_MAP_FLOAT_OOB_FILL_NONE);
}

extern "C" void kernel_launch(void* const* d_in, const int* in_sizes, int n_in,
                              void* d_out, int out_size)
{
    (void)in_sizes; (void)n_in; (void)out_size;
    const float* x     = (const float*)d_in[0];
    const float* Wq    = (const float*)d_in[1];
    const float* bq    = (const float*)d_in[2];
    const float* Wk    = (const float*)d_in[3];
    const float* bk    = (const float*)d_in[4];
    const float* Wv    = (const float*)d_in[5];
    const float* bv    = (const float*)d_in[6];
    const float* gamma = (const float*)d_in[7];
    float* out = (float*)d_out;

    EncodeFn enc = nullptr;
    cudaDriverEntryPointQueryResult qr;
    cudaGetDriverEntryPointByVersion("cuTensorMapEncodeTiled", (void**)&enc, 12000,
                                     cudaEnableDefault, &qr);

    void *pqk, *pvb, *peb, *pxT, *pwr, *pwqk, *pbqk, *prs;
    cudaGetSymbolAddress(&pqk,  g_qkh);
    cudaGetSymbolAddress(&pvb,  g_vb);
    cudaGetSymbolAddress(&peb,  g_eb);
    cudaGetSymbolAddress(&pxT,  g_xTh);
    cudaGetSymbolAddress(&pwr,  g_wrh);
    cudaGetSymbolAddress(&pwqk, g_wqkh);
    cudaGetSymbolAddress(&pbqk, g_bqk);
    cudaGetSymbolAddress(&prs,  g_rs);

    CUtensorMap tmXT_A64, tmXT_B, tmWQK, tmWV, tmQKa, tmQKb, tmVb, tmEb;
    build_tm(enc, &tmXT_A64, pxT, CC, NN, BB, (uint64_t)CC * 2, (uint64_t)NN * CC * 2, 64, 64);
    build_tm(enc, &tmXT_B,   pxT, CC, NN, BB, (uint64_t)CC * 2, (uint64_t)NN * CC * 2, 64, 128);
    build_tm(enc, &tmWQK, pwqk, CC, QK, 1, (uint64_t)CC * 2, (uint64_t)QK * CC * 2, 64, 128);
    build_tm(enc, &tmWV,  pwr,  CC, CC, 1, (uint64_t)CC * 2, (uint64_t)CC * CC * 2, 64, 128);
    build_tm(enc, &tmQKa, pqk, QK, NN, BB, (uint64_t)QK * 2, (uint64_t)NN * QK * 2, 64, 128);
    build_tm(enc, &tmQKb, pqk, QK, NN, BB, (uint64_t)QK * 2, (uint64_t)NN * QK * 2, 64, 128);
    build_tm(enc, &tmVb, pvb, NN, CC, BB, (uint64_t)NN * 2, (uint64_t)CC * NN * 2, 64, 128);
    build_tm(enc, &tmEb, peb, NN, NN, BB, (uint64_t)NN * 2, (uint64_t)NN * NN * 2, 64, 128);

    constexpr int DS1 = NSTAGE * (64 * 128 + B16_BY) + 1024;
    cudaFuncSetAttribute(qkproj_kernel, cudaFuncAttributeMaxDynamicSharedMemorySize, DS1);
    cudaFuncSetAttribute(gemm8w_kernel<0>, cudaFuncAttributeMaxDynamicSharedMemorySize, G8_DSMEM);
    cudaFuncSetAttribute(gemm8w_kernel<1>, cudaFuncAttributeMaxDynamicSharedMemorySize, G8_DSMEM);

    float* frs = (float*)prs;

    // 1. fused prep: xT transpose/convert + weight conversion + rs zero
    fusedprep_kernel<<<dim3(NN / 32, CC / 32, BB), 256>>>(x, Wv, Wq, bq, Wk, bk);
    // 2. qk projection: 128 CTAs, K=512, fp16 out
    qkproj_kernel<<<dim3(1, NN / 64, BB), 544, DS1>>>(
        tmXT_A64, tmWQK, (const float*)pbqk, (__half*)pqk);
    // 3. v projection (8w, 2 CTAs/SM): g_vb[c][n] = bf16(Wv·xT^T + bv), K=512
    gemm8w_kernel<0><<<dim3(NN / 128, CC / 128, BB), 288, G8_DSMEM>>>(
        tmWV, tmXT_B, CC, 0, 0, 1, 0, 0, 0, bv, frs, gamma,
        pvb, (size_t)CC * NN, NN);
    // 4. scores (8w): g_eb[i][j] = bf16(exp(q·k)), fp32 rowsums, K=64
    gemm8w_kernel<0><<<dim3(NN / 128, NN / 128, BB), 288, G8_DSMEM>>>(
        tmQKa, tmQKb, DD, 2, 1, 1, 0, DD, 0, nullptr, frs, gamma,
        peb, (size_t)NN * NN, NN);
    // 5. AV (8w, bf16 mma): out = gamma*(v·e^T)/rs + x, K=4096
    //    c-tiles fastest -> e tile shared in L2
    gemm8w_kernel<1><<<dim3(CC / 128, NN / 128, BB), 288, G8_DSMEM>>>(
        tmVb, tmEb, NN, 1, 1, 1, 0, 0, 1, x, frs, gamma,
        out, (size_t)CC * NN, NN);
}